// round 2
// baseline (speedup 1.0000x reference)
#include <cuda_runtime.h>

// Problem constants
#define BATCH   2
#define S_LEN   1024
#define D_DIM   1024
#define NHEAD   16
#define HD      64
#define NMEM    12          // 3*L
#define SCALE   0.125f      // 1/sqrt(64)

// ---------------------------------------------------------------------------
// Scratch (device globals: allocation-free)
// ---------------------------------------------------------------------------
__device__ float g_memln[(size_t)24576 * 1024];   // (B*S*M, D) LayerNorm'd mem rows
__device__ float g_rkv  [(size_t)24576 * 2048];   // (B*S*M, 2D): cols [0,1024)=rk, [1024,2048)=rv
__device__ float g_merged[(size_t)2048 * 1024];   // (B*S, D) attention output

// ---------------------------------------------------------------------------
// SGEMM (NT): C[m,n] = sum_k A[m,k]*B[n,k] + bias[n]
// BM=BN=128, BK=8, 256 threads, 8x8 microtile.
// EPI==0: plain row-major store to C (ldc = N)
// EPI==1: qkv scatter — row=(b*S+s), col in [0,3072): part(q/k/v), head, d
// ---------------------------------------------------------------------------
template<int EPI>
__global__ void __launch_bounds__(256, 2)
sgemm_nt(const float* __restrict__ A, const float* __restrict__ B,
         const float* __restrict__ bias, float* __restrict__ C,
         int M, int N, int K,
         float* __restrict__ oQ, float* __restrict__ oK, float* __restrict__ oV)
{
    __shared__ float As[8][128];
    __shared__ float Bs[8][128];

    const int tid = threadIdx.x;
    const int m0 = blockIdx.y * 128;
    const int n0 = blockIdx.x * 128;
    const int tx = tid & 15;       // col group
    const int ty = tid >> 4;       // row group
    const int lr = tid >> 1;       // 0..127 load row
    const int lc = (tid & 1) << 2; // 0 or 4

    const float* Ap = A + (size_t)(m0 + lr) * K + lc;
    const float* Bp = B + (size_t)(n0 + lr) * K + lc;

    float acc[8][8];
#pragma unroll
    for (int i = 0; i < 8; i++)
#pragma unroll
        for (int j = 0; j < 8; j++) acc[i][j] = 0.f;

    for (int k0 = 0; k0 < K; k0 += 8) {
        float4 av = *(const float4*)(Ap + k0);
        float4 bv = *(const float4*)(Bp + k0);
        As[lc + 0][lr] = av.x; As[lc + 1][lr] = av.y;
        As[lc + 2][lr] = av.z; As[lc + 3][lr] = av.w;
        Bs[lc + 0][lr] = bv.x; Bs[lc + 1][lr] = bv.y;
        Bs[lc + 2][lr] = bv.z; Bs[lc + 3][lr] = bv.w;
        __syncthreads();
#pragma unroll
        for (int kk = 0; kk < 8; kk++) {
            float a[8], bb[8];
            *(float4*)&a[0]  = *(const float4*)&As[kk][ty * 8];
            *(float4*)&a[4]  = *(const float4*)&As[kk][ty * 8 + 4];
            *(float4*)&bb[0] = *(const float4*)&Bs[kk][tx * 8];
            *(float4*)&bb[4] = *(const float4*)&Bs[kk][tx * 8 + 4];
#pragma unroll
            for (int i = 0; i < 8; i++)
#pragma unroll
                for (int j = 0; j < 8; j++)
                    acc[i][j] = fmaf(a[i], bb[j], acc[i][j]);
        }
        __syncthreads();
    }

#pragma unroll
    for (int i = 0; i < 8; i++) {
        int row = m0 + ty * 8 + i;
#pragma unroll
        for (int j = 0; j < 8; j++) {
            int col = n0 + tx * 8 + j;
            float v = acc[i][j] + bias[col];
            if (EPI == 0) {
                C[(size_t)row * N + col] = v;
            } else {
                int part = col >> 10;            // 0:q 1:k 2:v
                int rem  = col & 1023;
                int h = rem >> 6, d = rem & 63;
                int b = row >> 10, s = row & 1023;
                float* dst = (part == 0) ? oQ : (part == 1) ? oK : oV;
                dst[(size_t)(((b * NHEAD + h) << 10) + s) * HD + d] = v;
            }
        }
    }
}

// ---------------------------------------------------------------------------
// Gather mem rows from past_{q,k,v} + LayerNorm over D (two-pass, eps=1e-5)
// row = (b*S + s)*12 + j ; j in [0,4)->past_q[l=j], [4,8)->past_k, [8,12)->past_v
// mem[b,s,j, h*64+d] = past[l, b, h, s, d]
// ---------------------------------------------------------------------------
__device__ __forceinline__ float blockReduceSum(float v, float* red)
{
    __syncthreads();
    int lane = threadIdx.x & 31, wid = threadIdx.x >> 5;
#pragma unroll
    for (int o = 16; o; o >>= 1) v += __shfl_xor_sync(0xffffffffu, v, o);
    if (lane == 0) red[wid] = v;
    __syncthreads();
    if (wid == 0) {
        v = (lane < 8) ? red[lane] : 0.f;
#pragma unroll
        for (int o = 4; o; o >>= 1) v += __shfl_xor_sync(0xffffffffu, v, o);
        if (lane == 0) red[0] = v;
    }
    __syncthreads();
    return red[0];
}

__global__ void mem_ln_kernel(const float* __restrict__ pq,
                              const float* __restrict__ pk,
                              const float* __restrict__ pv)
{
    __shared__ float red[32];
    int row = blockIdx.x;                 // 0..24575
    int j  = row % NMEM;
    int bs = row / NMEM;
    int s = bs & 1023, b = bs >> 10;
    int l = j & 3;
    const float* src = (j < 4) ? pq : (j < 8) ? pk : pv;
    // (((l*B + b)*H + h)*S + s)*64 + d
    size_t base = (size_t)(l * BATCH + b) * (NHEAD * S_LEN * HD) + (size_t)s * HD;

    int t = threadIdx.x;
    float vals[4];
    float sum = 0.f;
#pragma unroll
    for (int u = 0; u < 4; u++) {
        int c = t + (u << 8);
        int h = c >> 6, d = c & 63;
        float v = __ldg(src + base + (size_t)h * (S_LEN * HD) + d);
        vals[u] = v; sum += v;
    }
    sum = blockReduceSum(sum, red);
    float mean = sum * (1.f / 1024.f);
    float sq = 0.f;
#pragma unroll
    for (int u = 0; u < 4; u++) { float dv = vals[u] - mean; sq += dv * dv; }
    sq = blockReduceSum(sq, red);
    float inv = rsqrtf(sq * (1.f / 1024.f) + 1e-5f);

    float* orow = g_memln + (size_t)row * 1024;
#pragma unroll
    for (int u = 0; u < 4; u++) orow[t + (u << 8)] = (vals[u] - mean) * inv;
}

// ---------------------------------------------------------------------------
// Fused causal token attention + 12-slot memory attention (online softmax).
// grid: (S/32, B*H), block 256 = (8 key-groups) x (32 queries)
// thread (tx in [0,8), qi in [0,32)) owns query qt0+qi and d-slice tx*8..tx*8+7
// ---------------------------------------------------------------------------
__global__ void __launch_bounds__(256, 2)
attn_kernel(const float* __restrict__ qg, const float* __restrict__ kg,
            const float* __restrict__ vg)
{
    __shared__ float ks[32][68];
    __shared__ float vs[32][68];
    __shared__ float ps[32][33];

    const int tid = threadIdx.x;
    const int tx = tid & 7;
    const int qi = tid >> 3;
    const int bh = blockIdx.y;
    const int b = bh >> 4, h = bh & 15;
    const int qt0 = blockIdx.x << 5;
    const int sq = qt0 + qi;
    const int c0 = tx << 3;

    float qreg[64];
    {
        const float4* qp = (const float4*)(qg + ((size_t)bh * 1024 + sq) * 64);
#pragma unroll
        for (int i = 0; i < 16; i++) ((float4*)qreg)[i] = __ldg(qp + i);
    }

    float m_i = -1e30f, l_i = 0.f;
    float acc[8];
#pragma unroll
    for (int i = 0; i < 8; i++) acc[i] = 0.f;

    const float* kbase = kg + (size_t)bh * 1024 * 64;
    const float* vbase = vg + (size_t)bh * 1024 * 64;

    // ---------------- token (causal) part ----------------
    for (int kt0 = 0; kt0 <= qt0; kt0 += 32) {
        __syncthreads();
        {
            const float4* kp = (const float4*)(kbase + (size_t)(kt0 + qi) * 64 + c0);
            const float4* vp = (const float4*)(vbase + (size_t)(kt0 + qi) * 64 + c0);
            float4 k0v = __ldg(kp), k1v = __ldg(kp + 1);
            float4 v0v = __ldg(vp), v1v = __ldg(vp + 1);
            *(float4*)&ks[qi][c0]     = k0v;
            *(float4*)&ks[qi][c0 + 4] = k1v;
            *(float4*)&vs[qi][c0]     = v0v;
            *(float4*)&vs[qi][c0 + 4] = v1v;
        }
        __syncthreads();

        float sc[4];
#pragma unroll
        for (int u = 0; u < 4; u++) {
            int kj = tx + (u << 3);
            float s = 0.f;
#pragma unroll
            for (int i = 0; i < 16; i++) {
                float4 kv = *(const float4*)&ks[kj][i << 2];
                s = fmaf(qreg[4 * i + 0], kv.x, s);
                s = fmaf(qreg[4 * i + 1], kv.y, s);
                s = fmaf(qreg[4 * i + 2], kv.z, s);
                s = fmaf(qreg[4 * i + 3], kv.w, s);
            }
            sc[u] = (kt0 + kj <= sq) ? s * SCALE : -1e30f;
        }
        float tmax = fmaxf(fmaxf(sc[0], sc[1]), fmaxf(sc[2], sc[3]));
#pragma unroll
        for (int o = 1; o < 8; o <<= 1)
            tmax = fmaxf(tmax, __shfl_xor_sync(0xffffffffu, tmax, o));
        float m_new = fmaxf(m_i, tmax);
        float corr = __expf(m_i - m_new);
        float psum = 0.f;
#pragma unroll
        for (int u = 0; u < 4; u++) {
            float p = __expf(sc[u] - m_new);
            ps[qi][tx + (u << 3)] = p;
            psum += p;
        }
#pragma unroll
        for (int o = 1; o < 8; o <<= 1)
            psum += __shfl_xor_sync(0xffffffffu, psum, o);
        l_i = l_i * corr + psum;
        m_i = m_new;
#pragma unroll
        for (int i = 0; i < 8; i++) acc[i] *= corr;
        __syncwarp();
#pragma unroll 8
        for (int kj = 0; kj < 32; kj++) {
            float p = ps[qi][kj];
            float4 v0 = *(const float4*)&vs[kj][c0];
            float4 v1 = *(const float4*)&vs[kj][c0 + 4];
            acc[0] = fmaf(p, v0.x, acc[0]);
            acc[1] = fmaf(p, v0.y, acc[1]);
            acc[2] = fmaf(p, v0.z, acc[2]);
            acc[3] = fmaf(p, v0.w, acc[3]);
            acc[4] = fmaf(p, v1.x, acc[4]);
            acc[5] = fmaf(p, v1.y, acc[5]);
            acc[6] = fmaf(p, v1.z, acc[6]);
            acc[7] = fmaf(p, v1.w, acc[7]);
        }
    }

    // ---------------- memory part (12 slots from g_rkv) ----------------
    const size_t rrow0 = (size_t)(b * 1024 + sq) * NMEM;
    const float* rkbase = g_rkv + rrow0 * 2048 + h * 64;

    float s0, s1 = -1e30f;
    {
        const float4* rp = (const float4*)(rkbase + (size_t)tx * 2048);
        float s = 0.f;
#pragma unroll
        for (int i = 0; i < 16; i++) {
            float4 kv = __ldg(rp + i);
            s = fmaf(qreg[4 * i + 0], kv.x, s);
            s = fmaf(qreg[4 * i + 1], kv.y, s);
            s = fmaf(qreg[4 * i + 2], kv.z, s);
            s = fmaf(qreg[4 * i + 3], kv.w, s);
        }
        s0 = s * SCALE;
    }
    if (tx < 4) {
        const float4* rp = (const float4*)(rkbase + (size_t)(tx + 8) * 2048);
        float s = 0.f;
#pragma unroll
        for (int i = 0; i < 16; i++) {
            float4 kv = __ldg(rp + i);
            s = fmaf(qreg[4 * i + 0], kv.x, s);
            s = fmaf(qreg[4 * i + 1], kv.y, s);
            s = fmaf(qreg[4 * i + 2], kv.z, s);
            s = fmaf(qreg[4 * i + 3], kv.w, s);
        }
        s1 = s * SCALE;
    }
    float tmax = fmaxf(s0, s1);
#pragma unroll
    for (int o = 1; o < 8; o <<= 1)
        tmax = fmaxf(tmax, __shfl_xor_sync(0xffffffffu, tmax, o));
    float m_new = fmaxf(m_i, tmax);
    float corr = __expf(m_i - m_new);

    __syncwarp();   // prior ps reads complete before overwrite
    float p0 = __expf(s0 - m_new);
    ps[qi][tx] = p0;
    float psum = p0;
    if (tx < 4) {
        float p1 = __expf(s1 - m_new);
        ps[qi][tx + 8] = p1;
        psum += p1;
    }
#pragma unroll
    for (int o = 1; o < 8; o <<= 1)
        psum += __shfl_xor_sync(0xffffffffu, psum, o);
    l_i = l_i * corr + psum;
#pragma unroll
    for (int i = 0; i < 8; i++) acc[i] *= corr;
    __syncwarp();

    const float* rvbase = rkbase + 1024 + c0;
#pragma unroll
    for (int m = 0; m < NMEM; m++) {
        float p = ps[qi][m];
        const float4* rp = (const float4*)(rvbase + (size_t)m * 2048);
        float4 v0 = __ldg(rp), v1 = __ldg(rp + 1);
        acc[0] = fmaf(p, v0.x, acc[0]);
        acc[1] = fmaf(p, v0.y, acc[1]);
        acc[2] = fmaf(p, v0.z, acc[2]);
        acc[3] = fmaf(p, v0.w, acc[3]);
        acc[4] = fmaf(p, v1.x, acc[4]);
        acc[5] = fmaf(p, v1.y, acc[5]);
        acc[6] = fmaf(p, v1.z, acc[6]);
        acc[7] = fmaf(p, v1.w, acc[7]);
    }

    float inv = 1.f / l_i;
    float* op = g_merged + (size_t)(b * 1024 + sq) * 1024 + h * 64 + c0;
    float4 o0 = make_float4(acc[0] * inv, acc[1] * inv, acc[2] * inv, acc[3] * inv);
    float4 o1 = make_float4(acc[4] * inv, acc[5] * inv, acc[6] * inv, acc[7] * inv);
    *(float4*)op = o0;
    *((float4*)op + 1) = o1;
}

// ---------------------------------------------------------------------------
// launch
// ---------------------------------------------------------------------------
extern "C" void kernel_launch(void* const* d_in, const int* in_sizes, int n_in,
                              void* d_out, int out_size)
{
    const float* x     = (const float*)d_in[0];
    const float* pastk = (const float*)d_in[1];
    const float* pastv = (const float*)d_in[2];
    const float* pastq = (const float*)d_in[3];
    const float* Wqkv  = (const float*)d_in[4];
    const float* bqkv  = (const float*)d_in[5];
    const float* Wout  = (const float*)d_in[6];
    const float* bout  = (const float*)d_in[7];

    float* out = (float*)d_out;                 // (B,S,D)
    float* oK  = out + (size_t)2097152;         // (B,H,S,hd)
    float* oV  = out + (size_t)2 * 2097152;
    float* oQ  = out + (size_t)3 * 2097152;

    // Resolve scratch symbols once (first call is the uncaptured correctness
    // run; capture call then does launches only).
    static float* s_memln = nullptr;
    static float* s_rkv = nullptr;
    static float* s_merged = nullptr;
    if (!s_memln) {
        cudaGetSymbolAddress((void**)&s_memln, g_memln);
        cudaGetSymbolAddress((void**)&s_rkv, g_rkv);
        cudaGetSymbolAddress((void**)&s_merged, g_merged);
    }

    // 1) qkv projection, scatter q/k/v into output regions (B,H,S,hd)
    {
        dim3 g(3072 / 128, 2048 / 128);
        sgemm_nt<1><<<g, 256>>>(x, Wqkv, bqkv, nullptr, 2048, 3072, 1024, oQ, oK, oV);
    }
    // 2) mem gather + LayerNorm
    mem_ln_kernel<<<24576, 256>>>(pastq, pastk, pastv);
    // 3) rk/rv projection: memLN @ [Wk;Wv]^T + [bk;bv]
    {
        dim3 g(2048 / 128, 24576 / 128);
        sgemm_nt<0><<<g, 256>>>(s_memln, Wqkv + (size_t)1024 * 1024, bqkv + 1024,
                                s_rkv, 24576, 2048, 1024, nullptr, nullptr, nullptr);
    }
    // 4) fused attention (token causal + memory slots)
    {
        dim3 g(1024 / 32, BATCH * NHEAD);
        attn_kernel<<<g, 256>>>(oQ, oK, oV);
    }
    // 5) output projection
    {
        dim3 g(1024 / 128, 2048 / 128);
        sgemm_nt<0><<<g, 256>>>(s_merged, Wout, bout, out, 2048, 1024, 1024,
                                nullptr, nullptr, nullptr);
    }
}

// round 4
// speedup vs baseline: 2.5520x; 2.5520x over previous
#include <cuda_runtime.h>
#include <cstdint>

// Problem constants
#define BATCH   2
#define S_LEN   1024
#define D_DIM   1024
#define NHEAD   16
#define HD      64
#define NMEM    12          // 3*L
#define SCALE   0.125f      // 1/sqrt(64)

// ---------------------------------------------------------------------------
// Scratch (device globals: allocation-free)
// ---------------------------------------------------------------------------
__device__ float g_memln[(size_t)24576 * 1024];   // (B*S*M, D) LN'd mem rows (tf32-rounded)
__device__ float g_rkv  [(size_t)24576 * 2048];   // (B*S*M, 2D): [0,1024)=rk, [1024,2048)=rv
__device__ float g_merged[(size_t)2048 * 1024];   // (B*S, D) attention output (tf32-rounded)
__device__ float g_xr   [(size_t)2048 * 1024];    // tf32-rounded x
__device__ float g_wqkv [(size_t)3072 * 1024];    // tf32-rounded Wqkv
__device__ float g_wout [(size_t)1024 * 1024];    // tf32-rounded Wout

// ---------------------------------------------------------------------------
// Helpers
// ---------------------------------------------------------------------------
__device__ __forceinline__ uint32_t smem_u32(const void* p) {
    uint32_t a;
    asm("{ .reg .u64 t; cvta.to.shared.u64 t, %1; cvt.u32.u64 %0, t; }" : "=r"(a) : "l"(p));
    return a;
}
__device__ __forceinline__ float tf32r(float x) {
    uint32_t u;
    asm("cvt.rna.tf32.f32 %0, %1;" : "=r"(u) : "f"(x));
    return __uint_as_float(u);
}
__device__ __forceinline__ void cp16(uint32_t dst, const void* src) {
    asm volatile("cp.async.cg.shared.global [%0], [%1], 16;" :: "r"(dst), "l"(src));
}
__device__ __forceinline__ void ldsm4(uint32_t* r, uint32_t addr) {
    asm volatile("ldmatrix.sync.aligned.m8n8.x4.shared.b16 {%0,%1,%2,%3}, [%4];"
                 : "=r"(r[0]), "=r"(r[1]), "=r"(r[2]), "=r"(r[3]) : "r"(addr));
}
__device__ __forceinline__ void mma8(float* c, const uint32_t* a, const uint32_t* b) {
    asm volatile("mma.sync.aligned.m16n8k8.row.col.f32.tf32.tf32.f32 "
                 "{%0,%1,%2,%3}, {%4,%5,%6,%7}, {%8,%9}, {%0,%1,%2,%3};"
                 : "+f"(c[0]), "+f"(c[1]), "+f"(c[2]), "+f"(c[3])
                 : "r"(a[0]), "r"(a[1]), "r"(a[2]), "r"(a[3]), "r"(b[0]), "r"(b[1]));
}

// ---------------------------------------------------------------------------
// tf32 GEMM (NT): C[m,n] = sum_k A[m,k]*B[n,k] + bias[n]
// A, B must be tf32-rounded fp32. Tile 128x128, BK=16, 256 thr (8 warps 2x4),
// warp tile 64x32 (4 m-tiles x 4 n-tiles of m16n8k8), cp.async double buffer.
// EPI==0: row-major store, ldc=N.  EPI==1: qkv scatter.
// ---------------------------------------------------------------------------
template<int EPI>
__global__ void __launch_bounds__(256)
gemm_tf32(const float* __restrict__ A, const float* __restrict__ B,
          const float* __restrict__ bias, float* __restrict__ C,
          int M, int N, int K,
          float* __restrict__ oQ, float* __restrict__ oK, float* __restrict__ oV)
{
    __shared__ float sA[2][128][20];   // row stride 80B
    __shared__ float sB[2][128][20];

    const int tid = threadIdx.x;
    const int lane = tid & 31, wid = tid >> 5;
    const int m0 = blockIdx.y << 7, n0 = blockIdx.x << 7;
    const int wm = (wid & 1) << 6;     // 0 / 64
    const int wn = (wid >> 1) << 5;    // 0 / 32 / 64 / 96

    // global -> smem mapping: thread covers 2 x 16B segs of one row
    const int grow = tid >> 1;
    const int gseg = (tid & 1) << 1;   // seg pair {0,1} or {2,3}
    const float* Ag = A + (size_t)(m0 + grow) * K + (gseg << 2);
    const float* Bg = B + (size_t)(n0 + grow) * K + (gseg << 2);
    const uint32_t sOffLd = (uint32_t)(grow * 80 + (gseg << 4));

    // ldmatrix per-thread address components
    const int tIn = lane & 7, sel = lane >> 3;
    const int rAl = tIn + ((sel & 1) << 3);   // +8 for sel 1,3
    const int cAl = (sel & 2) << 1;           // +4 words for sel 2,3
    const int rBl = tIn + ((sel & 2) << 2);   // +8 for sel 2,3
    const int cBl = (sel & 1) << 2;           // +4 words for sel 1,3

    const uint32_t aBase = smem_u32(&sA[0][0][0]);
    const uint32_t bBase = smem_u32(&sB[0][0][0]);

#define G_LOAD(slot, kblk) do {                                                \
    const float* _a = Ag + ((kblk) << 4);                                      \
    const float* _b = Bg + ((kblk) << 4);                                      \
    uint32_t _da = aBase + (uint32_t)(slot) * 10240u + sOffLd;                 \
    uint32_t _db = bBase + (uint32_t)(slot) * 10240u + sOffLd;                 \
    cp16(_da, _a); cp16(_da + 16, _a + 4);                                     \
    cp16(_db, _b); cp16(_db + 16, _b + 4);                                     \
    asm volatile("cp.async.commit_group;" ::: "memory");                       \
} while (0)

    float c[4][4][4];
#pragma unroll
    for (int i = 0; i < 4; i++)
#pragma unroll
        for (int j = 0; j < 4; j++)
#pragma unroll
            for (int r = 0; r < 4; r++) c[i][j][r] = 0.f;

    const int kIters = K >> 4;
    G_LOAD(0, 0);
    G_LOAD(1, 1);

    for (int it = 0; it < kIters; ++it) {
        if (it + 2 < kIters)
            asm volatile("cp.async.wait_group 1;" ::: "memory");
        else
            asm volatile("cp.async.wait_group 0;" ::: "memory");
        __syncthreads();

        const int st = it & 1;
        const uint32_t aS = aBase + (uint32_t)st * 10240u;
        const uint32_t bS = bBase + (uint32_t)st * 10240u;

#pragma unroll
        for (int ks = 0; ks < 2; ++ks) {
            uint32_t a[4][4];
#pragma unroll
            for (int i = 0; i < 4; i++) {
                uint32_t ad = aS + (uint32_t)(((wm + i * 16 + rAl) * 20 + ks * 8 + cAl) << 2);
                ldsm4(a[i], ad);
            }
            uint32_t b[4][2];
#pragma unroll
            for (int j2 = 0; j2 < 2; j2++) {
                uint32_t r4[4];
                uint32_t bd = bS + (uint32_t)(((wn + j2 * 16 + rBl) * 20 + ks * 8 + cBl) << 2);
                ldsm4(r4, bd);
                b[2 * j2 + 0][0] = r4[0]; b[2 * j2 + 0][1] = r4[1];
                b[2 * j2 + 1][0] = r4[2]; b[2 * j2 + 1][1] = r4[3];
            }
#pragma unroll
            for (int i = 0; i < 4; i++)
#pragma unroll
                for (int j = 0; j < 4; j++)
                    mma8(c[i][j], a[i], b[j]);
        }
        __syncthreads();
        if (it + 2 < kIters) G_LOAD(st, it + 2);
    }
#undef G_LOAD

    // epilogue
    const int gro = lane >> 2;
    const int gco = (lane & 3) << 1;
#pragma unroll
    for (int i = 0; i < 4; i++) {
        const int r0 = m0 + wm + i * 16 + gro;
#pragma unroll
        for (int j = 0; j < 4; j++) {
            const int col = n0 + wn + j * 8 + gco;
            const float b0 = bias[col], b1 = bias[col + 1];
            if (EPI == 0) {
                float2 v0 = make_float2(c[i][j][0] + b0, c[i][j][1] + b1);
                float2 v1 = make_float2(c[i][j][2] + b0, c[i][j][3] + b1);
                *(float2*)(C + (size_t)r0 * N + col) = v0;
                *(float2*)(C + (size_t)(r0 + 8) * N + col) = v1;
            } else {
                const int part = col >> 10;
                const int rem  = col & 1023;
                const int h = rem >> 6, d = rem & 63;
                float* dst = (part == 0) ? oQ : (part == 1) ? oK : oV;
#pragma unroll
                for (int half = 0; half < 2; half++) {
                    const int row = r0 + half * 8;
                    const int bb = row >> 10, s = row & 1023;
                    float2 v = make_float2(c[i][j][2 * half] + b0,
                                           c[i][j][2 * half + 1] + b1);
                    *(float2*)(dst + (size_t)(((bb * NHEAD + h) << 10) + s) * HD + d) = v;
                }
            }
        }
    }
}

// ---------------------------------------------------------------------------
// tf32-round a buffer (float4 per thread)
// ---------------------------------------------------------------------------
__global__ void cvt_tf32_kernel(const float4* __restrict__ in, float4* __restrict__ out)
{
    int i = blockIdx.x * blockDim.x + threadIdx.x;
    float4 v = in[i];
    v.x = tf32r(v.x); v.y = tf32r(v.y); v.z = tf32r(v.z); v.w = tf32r(v.w);
    out[i] = v;
}

// ---------------------------------------------------------------------------
// Gather mem rows from past_{q,k,v} + LayerNorm over D (tf32-rounded output)
// ---------------------------------------------------------------------------
__device__ __forceinline__ float blockReduceSum(float v, float* red)
{
    __syncthreads();
    int lane = threadIdx.x & 31, wid = threadIdx.x >> 5;
#pragma unroll
    for (int o = 16; o; o >>= 1) v += __shfl_xor_sync(0xffffffffu, v, o);
    if (lane == 0) red[wid] = v;
    __syncthreads();
    if (wid == 0) {
        v = (lane < 8) ? red[lane] : 0.f;
#pragma unroll
        for (int o = 4; o; o >>= 1) v += __shfl_xor_sync(0xffffffffu, v, o);
        if (lane == 0) red[0] = v;
    }
    __syncthreads();
    return red[0];
}

__global__ void mem_ln_kernel(const float* __restrict__ pq,
                              const float* __restrict__ pk,
                              const float* __restrict__ pv)
{
    __shared__ float red[32];
    int row = blockIdx.x;
    int j  = row % NMEM;
    int bs = row / NMEM;
    int s = bs & 1023, b = bs >> 10;
    int l = j & 3;
    const float* src = (j < 4) ? pq : (j < 8) ? pk : pv;
    size_t base = (size_t)(l * BATCH + b) * (NHEAD * S_LEN * HD) + (size_t)s * HD;

    int t = threadIdx.x;
    float vals[4];
    float sum = 0.f;
#pragma unroll
    for (int u = 0; u < 4; u++) {
        int c = t + (u << 8);
        int h = c >> 6, d = c & 63;
        float v = __ldg(src + base + (size_t)h * (S_LEN * HD) + d);
        vals[u] = v; sum += v;
    }
    sum = blockReduceSum(sum, red);
    float mean = sum * (1.f / 1024.f);
    float sq = 0.f;
#pragma unroll
    for (int u = 0; u < 4; u++) { float dv = vals[u] - mean; sq += dv * dv; }
    sq = blockReduceSum(sq, red);
    float inv = rsqrtf(sq * (1.f / 1024.f) + 1e-5f);

    float* orow = g_memln + (size_t)row * 1024;
#pragma unroll
    for (int u = 0; u < 4; u++) orow[t + (u << 8)] = tf32r((vals[u] - mean) * inv);
}

// ---------------------------------------------------------------------------
// Fused causal token attention + 12-slot memory attention (online softmax).
// ---------------------------------------------------------------------------
__global__ void __launch_bounds__(256, 2)
attn_kernel(const float* __restrict__ qg, const float* __restrict__ kg,
            const float* __restrict__ vg)
{
    __shared__ float ks[32][68];
    __shared__ float vs[32][68];
    __shared__ float ps[32][33];

    const int tid = threadIdx.x;
    const int tx = tid & 7;
    const int qi = tid >> 3;
    const int bh = blockIdx.y;
    const int b = bh >> 4, h = bh & 15;
    const int qt0 = blockIdx.x << 5;
    const int sq = qt0 + qi;
    const int c0 = tx << 3;

    float qreg[64];
    {
        const float4* qp = (const float4*)(qg + ((size_t)bh * 1024 + sq) * 64);
#pragma unroll
        for (int i = 0; i < 16; i++) ((float4*)qreg)[i] = __ldg(qp + i);
    }

    float m_i = -1e30f, l_i = 0.f;
    float acc[8];
#pragma unroll
    for (int i = 0; i < 8; i++) acc[i] = 0.f;

    const float* kbase = kg + (size_t)bh * 1024 * 64;
    const float* vbase = vg + (size_t)bh * 1024 * 64;

    for (int kt0 = 0; kt0 <= qt0; kt0 += 32) {
        __syncthreads();
        {
            const float4* kp = (const float4*)(kbase + (size_t)(kt0 + qi) * 64 + c0);
            const float4* vp = (const float4*)(vbase + (size_t)(kt0 + qi) * 64 + c0);
            float4 k0v = __ldg(kp), k1v = __ldg(kp + 1);
            float4 v0v = __ldg(vp), v1v = __ldg(vp + 1);
            *(float4*)&ks[qi][c0]     = k0v;
            *(float4*)&ks[qi][c0 + 4] = k1v;
            *(float4*)&vs[qi][c0]     = v0v;
            *(float4*)&vs[qi][c0 + 4] = v1v;
        }
        __syncthreads();

        float sc[4];
#pragma unroll
        for (int u = 0; u < 4; u++) {
            int kj = tx + (u << 3);
            float s = 0.f;
#pragma unroll
            for (int i = 0; i < 16; i++) {
                float4 kv = *(const float4*)&ks[kj][i << 2];
                s = fmaf(qreg[4 * i + 0], kv.x, s);
                s = fmaf(qreg[4 * i + 1], kv.y, s);
                s = fmaf(qreg[4 * i + 2], kv.z, s);
                s = fmaf(qreg[4 * i + 3], kv.w, s);
            }
            sc[u] = (kt0 + kj <= sq) ? s * SCALE : -1e30f;
        }
        float tmax = fmaxf(fmaxf(sc[0], sc[1]), fmaxf(sc[2], sc[3]));
#pragma unroll
        for (int o = 1; o < 8; o <<= 1)
            tmax = fmaxf(tmax, __shfl_xor_sync(0xffffffffu, tmax, o));
        float m_new = fmaxf(m_i, tmax);
        float corr = __expf(m_i - m_new);
        float psum = 0.f;
#pragma unroll
        for (int u = 0; u < 4; u++) {
            float p = __expf(sc[u] - m_new);
            ps[qi][tx + (u << 3)] = p;
            psum += p;
        }
#pragma unroll
        for (int o = 1; o < 8; o <<= 1)
            psum += __shfl_xor_sync(0xffffffffu, psum, o);
        l_i = l_i * corr + psum;
        m_i = m_new;
#pragma unroll
        for (int i = 0; i < 8; i++) acc[i] *= corr;
        __syncwarp();
#pragma unroll 8
        for (int kj = 0; kj < 32; kj++) {
            float p = ps[qi][kj];
            float4 v0 = *(const float4*)&vs[kj][c0];
            float4 v1 = *(const float4*)&vs[kj][c0 + 4];
            acc[0] = fmaf(p, v0.x, acc[0]);
            acc[1] = fmaf(p, v0.y, acc[1]);
            acc[2] = fmaf(p, v0.z, acc[2]);
            acc[3] = fmaf(p, v0.w, acc[3]);
            acc[4] = fmaf(p, v1.x, acc[4]);
            acc[5] = fmaf(p, v1.y, acc[5]);
            acc[6] = fmaf(p, v1.z, acc[6]);
            acc[7] = fmaf(p, v1.w, acc[7]);
        }
    }

    // ---------------- memory part (12 slots from g_rkv) ----------------
    const size_t rrow0 = (size_t)(b * 1024 + sq) * NMEM;
    const float* rkbase = g_rkv + rrow0 * 2048 + h * 64;

    float s0, s1 = -1e30f;
    {
        const float4* rp = (const float4*)(rkbase + (size_t)tx * 2048);
        float s = 0.f;
#pragma unroll
        for (int i = 0; i < 16; i++) {
            float4 kv = __ldg(rp + i);
            s = fmaf(qreg[4 * i + 0], kv.x, s);
            s = fmaf(qreg[4 * i + 1], kv.y, s);
            s = fmaf(qreg[4 * i + 2], kv.z, s);
            s = fmaf(qreg[4 * i + 3], kv.w, s);
        }
        s0 = s * SCALE;
    }
    if (tx < 4) {
        const float4* rp = (const float4*)(rkbase + (size_t)(tx + 8) * 2048);
        float s = 0.f;
#pragma unroll
        for (int i = 0; i < 16; i++) {
            float4 kv = __ldg(rp + i);
            s = fmaf(qreg[4 * i + 0], kv.x, s);
            s = fmaf(qreg[4 * i + 1], kv.y, s);
            s = fmaf(qreg[4 * i + 2], kv.z, s);
            s = fmaf(qreg[4 * i + 3], kv.w, s);
        }
        s1 = s * SCALE;
    }
    float tmax = fmaxf(s0, s1);
#pragma unroll
    for (int o = 1; o < 8; o <<= 1)
        tmax = fmaxf(tmax, __shfl_xor_sync(0xffffffffu, tmax, o));
    float m_new = fmaxf(m_i, tmax);
    float corr = __expf(m_i - m_new);

    __syncwarp();
    float p0 = __expf(s0 - m_new);
    ps[qi][tx] = p0;
    float psum = p0;
    if (tx < 4) {
        float p1 = __expf(s1 - m_new);
        ps[qi][tx + 8] = p1;
        psum += p1;
    }
#pragma unroll
    for (int o = 1; o < 8; o <<= 1)
        psum += __shfl_xor_sync(0xffffffffu, psum, o);
    l_i = l_i * corr + psum;
#pragma unroll
    for (int i = 0; i < 8; i++) acc[i] *= corr;
    __syncwarp();

    const float* rvbase = rkbase + 1024 + c0;
#pragma unroll
    for (int m = 0; m < NMEM; m++) {
        float p = ps[qi][m];
        const float4* rp = (const float4*)(rvbase + (size_t)m * 2048);
        float4 v0 = __ldg(rp), v1 = __ldg(rp + 1);
        acc[0] = fmaf(p, v0.x, acc[0]);
        acc[1] = fmaf(p, v0.y, acc[1]);
        acc[2] = fmaf(p, v0.z, acc[2]);
        acc[3] = fmaf(p, v0.w, acc[3]);
        acc[4] = fmaf(p, v1.x, acc[4]);
        acc[5] = fmaf(p, v1.y, acc[5]);
        acc[6] = fmaf(p, v1.z, acc[6]);
        acc[7] = fmaf(p, v1.w, acc[7]);
    }

    float inv = 1.f / l_i;
    float* op = g_merged + (size_t)(b * 1024 + sq) * 1024 + h * 64 + c0;
    float4 o0 = make_float4(tf32r(acc[0] * inv), tf32r(acc[1] * inv),
                            tf32r(acc[2] * inv), tf32r(acc[3] * inv));
    float4 o1 = make_float4(tf32r(acc[4] * inv), tf32r(acc[5] * inv),
                            tf32r(acc[6] * inv), tf32r(acc[7] * inv));
    *(float4*)op = o0;
    *((float4*)op + 1) = o1;
}

// ---------------------------------------------------------------------------
// launch
// ---------------------------------------------------------------------------
extern "C" void kernel_launch(void* const* d_in, const int* in_sizes, int n_in,
                              void* d_out, int out_size)
{
    const float* x     = (const float*)d_in[0];
    const float* pastk = (const float*)d_in[1];
    const float* pastv = (const float*)d_in[2];
    const float* pastq = (const float*)d_in[3];
    const float* Wqkv  = (const float*)d_in[4];
    const float* bqkv  = (const float*)d_in[5];
    const float* Wout  = (const float*)d_in[6];
    const float* bout  = (const float*)d_in[7];

    float* out = (float*)d_out;                 // (B,S,D)
    float* oK  = out + (size_t)2097152;         // (B,H,S,hd)
    float* oV  = out + (size_t)2 * 2097152;
    float* oQ  = out + (size_t)3 * 2097152;

    static float* s_memln = nullptr;
    static float* s_rkv = nullptr;
    static float* s_merged = nullptr;
    static float* s_xr = nullptr;
    static float* s_wqkv = nullptr;
    static float* s_wout = nullptr;
    if (!s_memln) {
        cudaGetSymbolAddress((void**)&s_memln, g_memln);
        cudaGetSymbolAddress((void**)&s_rkv, g_rkv);
        cudaGetSymbolAddress((void**)&s_merged, g_merged);
        cudaGetSymbolAddress((void**)&s_xr, g_xr);
        cudaGetSymbolAddress((void**)&s_wqkv, g_wqkv);
        cudaGetSymbolAddress((void**)&s_wout, g_wout);
    }

    // 0) tf32-round GEMM operands
    cvt_tf32_kernel<<<2048, 256>>>((const float4*)x,    (float4*)s_xr);
    cvt_tf32_kernel<<<3072, 256>>>((const float4*)Wqkv, (float4*)s_wqkv);
    cvt_tf32_kernel<<<1024, 256>>>((const float4*)Wout, (float4*)s_wout);

    // 1) qkv projection (tensor core tf32), scatter q/k/v into output regions
    {
        dim3 g(3072 / 128, 2048 / 128);
        gemm_tf32<1><<<g, 256>>>(s_xr, s_wqkv, bqkv, nullptr, 2048, 3072, 1024,
                                 oQ, oK, oV);
    }
    // 2) mem gather + LayerNorm (tf32-rounded output)
    mem_ln_kernel<<<24576, 256>>>(pastq, pastk, pastv);
    // 3) rk/rv projection (tensor core tf32)
    {
        dim3 g(2048 / 128, 24576 / 128);
        gemm_tf32<0><<<g, 256>>>(s_memln, s_wqkv + (size_t)1024 * 1024,
                                 bqkv + 1024, s_rkv, 24576, 2048, 1024,
                                 nullptr, nullptr, nullptr);
    }
    // 4) fused attention (token causal + memory slots)
    {
        dim3 g(1024 / 32, BATCH * NHEAD);
        attn_kernel<<<g, 256>>>(oQ, oK, oV);
    }
    // 5) output projection (tensor core tf32)
    {
        dim3 g(1024 / 128, 2048 / 128);
        gemm_tf32<0><<<g, 256>>>(s_merged, s_wout, bout, out, 2048, 1024, 1024,
                                 nullptr, nullptr, nullptr);
    }
}

// round 5
// speedup vs baseline: 2.8373x; 1.1118x over previous
#include <cuda_runtime.h>
#include <cstdint>

// Problem constants
#define BATCH   2
#define S_LEN   1024
#define D_DIM   1024
#define NHEAD   16
#define HD      64
#define NMEM    12          // 3*L
#define SCALE   0.125f      // 1/sqrt(64)

// ---------------------------------------------------------------------------
// Scratch (device globals: allocation-free)
// ---------------------------------------------------------------------------
__device__ float g_memln[(size_t)24576 * 1024];   // (B*S*M, D) LN'd mem rows (tf32-rounded)
__device__ float g_rkv  [(size_t)24576 * 2048];   // (B*S*M, 2D): [0,1024)=rk, [1024,2048)=rv
__device__ float g_merged[(size_t)2048 * 1024];   // (B*S, D) attention output (tf32-rounded)
__device__ float g_xr   [(size_t)2048 * 1024];    // tf32-rounded x
__device__ float g_wqkv [(size_t)3072 * 1024];    // tf32-rounded Wqkv
__device__ float g_wout [(size_t)1024 * 1024];    // tf32-rounded Wout

// ---------------------------------------------------------------------------
// Helpers
// ---------------------------------------------------------------------------
__device__ __forceinline__ uint32_t smem_u32(const void* p) {
    uint32_t a;
    asm("{ .reg .u64 t; cvta.to.shared.u64 t, %1; cvt.u32.u64 %0, t; }" : "=r"(a) : "l"(p));
    return a;
}
__device__ __forceinline__ float tf32r(float x) {
    uint32_t u;
    asm("cvt.rna.tf32.f32 %0, %1;" : "=r"(u) : "f"(x));
    return __uint_as_float(u);
}
__device__ __forceinline__ void cp16(uint32_t dst, const void* src) {
    asm volatile("cp.async.cg.shared.global [%0], [%1], 16;" :: "r"(dst), "l"(src));
}
__device__ __forceinline__ void ldsm4(uint32_t* r, uint32_t addr) {
    asm volatile("ldmatrix.sync.aligned.m8n8.x4.shared.b16 {%0,%1,%2,%3}, [%4];"
                 : "=r"(r[0]), "=r"(r[1]), "=r"(r[2]), "=r"(r[3]) : "r"(addr));
}
__device__ __forceinline__ void mma8(float* c, const uint32_t* a, const uint32_t* b) {
    asm volatile("mma.sync.aligned.m16n8k8.row.col.f32.tf32.tf32.f32 "
                 "{%0,%1,%2,%3}, {%4,%5,%6,%7}, {%8,%9}, {%0,%1,%2,%3};"
                 : "+f"(c[0]), "+f"(c[1]), "+f"(c[2]), "+f"(c[3])
                 : "r"(a[0]), "r"(a[1]), "r"(a[2]), "r"(a[3]), "r"(b[0]), "r"(b[1]));
}

// ===========================================================================
// BIG tf32 GEMM (NT): C[m,n] = sum_k A[m,k]*B[n,k] + bias[n]
// Block tile 256x128, BK=32, 3-stage cp.async pipeline, 256 threads (8 warps),
// warp tile 64x64 (4 m-subtiles x 8 n-subtiles of m16n8k8).
// Row padding: 36 floats -> ldmatrix banks 4r mod 32, conflict-free.
// EPI==0: row-major store. EPI==1: qkv scatter.
// Dynamic smem: 3*(256*36 + 128*36)*4 = 165888 bytes.
// ===========================================================================
#define GB_ASTG 36864u   // bytes per A stage (256*36*4)
#define GB_BSTG 18432u   // bytes per B stage (128*36*4)
#define GB_SMEM 165888

template<int EPI>
__global__ void __launch_bounds__(256, 1)
gemm_big(const float* __restrict__ A, const float* __restrict__ B,
         const float* __restrict__ bias, float* __restrict__ C,
         int M, int N, int K,
         float* __restrict__ oQ, float* __restrict__ oK, float* __restrict__ oV)
{
    extern __shared__ float smem[];
    const uint32_t aBase = smem_u32(smem);
    const uint32_t bBase = aBase + 3u * GB_ASTG;

    const int tid = threadIdx.x;
    const int lane = tid & 31, wid = tid >> 5;
    const int m0 = blockIdx.y << 8;          // 256-row tile
    const int n0 = blockIdx.x << 7;          // 128-col tile
    const int wm = (wid & 3) << 6;           // 0/64/128/192
    const int wn = (wid >> 2) << 6;          // 0/64

    // global->smem load mapping: thread covers one float4 in rows {r + 32p}
    const int grow = tid >> 3;               // 0..31
    const int gc4  = tid & 7;                // float4 index within 32-float row
    const float* Ag = A + (size_t)(m0 + grow) * K + (gc4 << 2);
    const float* Bg = B + (size_t)(n0 + grow) * K + (gc4 << 2);
    const uint32_t sOff = (uint32_t)((grow * 36 + (gc4 << 2)) << 2);

    // ldmatrix per-thread address components (same fragment map as proven R4)
    const int tIn = lane & 7, sel = lane >> 3;
    const int rAl = tIn + ((sel & 1) << 3);
    const int cAl = (sel & 2) << 1;
    const int rBl = tIn + ((sel & 2) << 2);
    const int cBl = (sel & 1) << 2;

#define GB_LOAD(stage, kb) do {                                                \
    const float* _a = Ag + ((kb) << 5);                                        \
    const float* _b = Bg + ((kb) << 5);                                        \
    const uint32_t _da = aBase + (uint32_t)(stage) * GB_ASTG + sOff;           \
    const uint32_t _db = bBase + (uint32_t)(stage) * GB_BSTG + sOff;           \
    _Pragma("unroll")                                                          \
    for (int _p = 0; _p < 8; _p++)                                             \
        cp16(_da + (uint32_t)_p * 4608u, _a + (size_t)(_p << 5) * K);          \
    _Pragma("unroll")                                                          \
    for (int _p = 0; _p < 4; _p++)                                             \
        cp16(_db + (uint32_t)_p * 4608u, _b + (size_t)(_p << 5) * K);          \
    asm volatile("cp.async.commit_group;" ::: "memory");                       \
} while (0)

    float c[4][8][4];
#pragma unroll
    for (int i = 0; i < 4; i++)
#pragma unroll
        for (int j = 0; j < 8; j++)
#pragma unroll
            for (int r = 0; r < 4; r++) c[i][j][r] = 0.f;

    const int NK = K >> 5;                   // 32-wide K stages
    GB_LOAD(0, 0);
    GB_LOAD(1, 1);

    for (int kb = 0; kb < NK; ++kb) {
        if (kb < NK - 1)
            asm volatile("cp.async.wait_group 1;" ::: "memory");
        else
            asm volatile("cp.async.wait_group 0;" ::: "memory");
        __syncthreads();

        // prefetch stage kb+2 into the buffer read at kb-1 (now free)
        if (kb + 2 < NK) {
            int ns = kb + 2; ns = ns - (ns / 3) * 3;
            GB_LOAD(ns, kb + 2);
        }

        int st = kb - (kb / 3) * 3;
        const uint32_t aS = aBase + (uint32_t)st * GB_ASTG;
        const uint32_t bS = bBase + (uint32_t)st * GB_BSTG;

#pragma unroll
        for (int ks = 0; ks < 4; ++ks) {
            uint32_t a[4][4];
#pragma unroll
            for (int i = 0; i < 4; i++)
                ldsm4(a[i], aS + (uint32_t)(((wm + i * 16 + rAl) * 36 + ks * 8 + cAl) << 2));
            uint32_t b[8][2];
#pragma unroll
            for (int j2 = 0; j2 < 4; j2++) {
                uint32_t r4[4];
                ldsm4(r4, bS + (uint32_t)(((wn + j2 * 16 + rBl) * 36 + ks * 8 + cBl) << 2));
                b[2 * j2 + 0][0] = r4[0]; b[2 * j2 + 0][1] = r4[1];
                b[2 * j2 + 1][0] = r4[2]; b[2 * j2 + 1][1] = r4[3];
            }
#pragma unroll
            for (int i = 0; i < 4; i++)
#pragma unroll
                for (int j = 0; j < 8; j++)
                    mma8(c[i][j], a[i], b[j]);
        }
    }
#undef GB_LOAD

    // epilogue
    const int gro = lane >> 2;
    const int gco = (lane & 3) << 1;
#pragma unroll
    for (int i = 0; i < 4; i++) {
        const int r0 = m0 + wm + i * 16 + gro;
#pragma unroll
        for (int j = 0; j < 8; j++) {
            const int col = n0 + wn + j * 8 + gco;
            const float b0 = bias[col], b1 = bias[col + 1];
            if (EPI == 0) {
                float2 v0 = make_float2(c[i][j][0] + b0, c[i][j][1] + b1);
                float2 v1 = make_float2(c[i][j][2] + b0, c[i][j][3] + b1);
                *(float2*)(C + (size_t)r0 * N + col) = v0;
                *(float2*)(C + (size_t)(r0 + 8) * N + col) = v1;
            } else {
                const int part = col >> 10;
                const int rem  = col & 1023;
                const int h = rem >> 6, d = rem & 63;
                float* dst = (part == 0) ? oQ : (part == 1) ? oK : oV;
#pragma unroll
                for (int half = 0; half < 2; half++) {
                    const int row = r0 + half * 8;
                    const int bb = row >> 10, s = row & 1023;
                    float2 v = make_float2(c[i][j][2 * half] + b0,
                                           c[i][j][2 * half + 1] + b1);
                    *(float2*)(dst + (size_t)(((bb * NHEAD + h) << 10) + s) * HD + d) = v;
                }
            }
        }
    }
}

// ---------------------------------------------------------------------------
// 128x128 tf32 GEMM (round-4 proven) — kept for GEMM3 (small grid)
// ---------------------------------------------------------------------------
template<int EPI>
__global__ void __launch_bounds__(256)
gemm_tf32(const float* __restrict__ A, const float* __restrict__ B,
          const float* __restrict__ bias, float* __restrict__ C,
          int M, int N, int K,
          float* __restrict__ oQ, float* __restrict__ oK, float* __restrict__ oV)
{
    __shared__ float sA[2][128][20];
    __shared__ float sB[2][128][20];

    const int tid = threadIdx.x;
    const int lane = tid & 31, wid = tid >> 5;
    const int m0 = blockIdx.y << 7, n0 = blockIdx.x << 7;
    const int wm = (wid & 1) << 6;
    const int wn = (wid >> 1) << 5;

    const int grow = tid >> 1;
    const int gseg = (tid & 1) << 1;
    const float* Ag = A + (size_t)(m0 + grow) * K + (gseg << 2);
    const float* Bg = B + (size_t)(n0 + grow) * K + (gseg << 2);
    const uint32_t sOffLd = (uint32_t)(grow * 80 + (gseg << 4));

    const int tIn = lane & 7, sel = lane >> 3;
    const int rAl = tIn + ((sel & 1) << 3);
    const int cAl = (sel & 2) << 1;
    const int rBl = tIn + ((sel & 2) << 2);
    const int cBl = (sel & 1) << 2;

    const uint32_t aBase = smem_u32(&sA[0][0][0]);
    const uint32_t bBase = smem_u32(&sB[0][0][0]);

#define G_LOAD(slot, kblk) do {                                                \
    const float* _a = Ag + ((kblk) << 4);                                      \
    const float* _b = Bg + ((kblk) << 4);                                      \
    uint32_t _da = aBase + (uint32_t)(slot) * 10240u + sOffLd;                 \
    uint32_t _db = bBase + (uint32_t)(slot) * 10240u + sOffLd;                 \
    cp16(_da, _a); cp16(_da + 16, _a + 4);                                     \
    cp16(_db, _b); cp16(_db + 16, _b + 4);                                     \
    asm volatile("cp.async.commit_group;" ::: "memory");                       \
} while (0)

    float c[4][4][4];
#pragma unroll
    for (int i = 0; i < 4; i++)
#pragma unroll
        for (int j = 0; j < 4; j++)
#pragma unroll
            for (int r = 0; r < 4; r++) c[i][j][r] = 0.f;

    const int kIters = K >> 4;
    G_LOAD(0, 0);
    G_LOAD(1, 1);

    for (int it = 0; it < kIters; ++it) {
        if (it + 2 < kIters)
            asm volatile("cp.async.wait_group 1;" ::: "memory");
        else
            asm volatile("cp.async.wait_group 0;" ::: "memory");
        __syncthreads();

        const int st = it & 1;
        const uint32_t aS = aBase + (uint32_t)st * 10240u;
        const uint32_t bS = bBase + (uint32_t)st * 10240u;

#pragma unroll
        for (int ks = 0; ks < 2; ++ks) {
            uint32_t a[4][4];
#pragma unroll
            for (int i = 0; i < 4; i++) {
                uint32_t ad = aS + (uint32_t)(((wm + i * 16 + rAl) * 20 + ks * 8 + cAl) << 2);
                ldsm4(a[i], ad);
            }
            uint32_t b[4][2];
#pragma unroll
            for (int j2 = 0; j2 < 2; j2++) {
                uint32_t r4[4];
                uint32_t bd = bS + (uint32_t)(((wn + j2 * 16 + rBl) * 20 + ks * 8 + cBl) << 2);
                ldsm4(r4, bd);
                b[2 * j2 + 0][0] = r4[0]; b[2 * j2 + 0][1] = r4[1];
                b[2 * j2 + 1][0] = r4[2]; b[2 * j2 + 1][1] = r4[3];
            }
#pragma unroll
            for (int i = 0; i < 4; i++)
#pragma unroll
                for (int j = 0; j < 4; j++)
                    mma8(c[i][j], a[i], b[j]);
        }
        __syncthreads();
        if (it + 2 < kIters) G_LOAD(st, it + 2);
    }
#undef G_LOAD

    const int gro = lane >> 2;
    const int gco = (lane & 3) << 1;
#pragma unroll
    for (int i = 0; i < 4; i++) {
        const int r0 = m0 + wm + i * 16 + gro;
#pragma unroll
        for (int j = 0; j < 4; j++) {
            const int col = n0 + wn + j * 8 + gco;
            const float b0 = bias[col], b1 = bias[col + 1];
            if (EPI == 0) {
                float2 v0 = make_float2(c[i][j][0] + b0, c[i][j][1] + b1);
                float2 v1 = make_float2(c[i][j][2] + b0, c[i][j][3] + b1);
                *(float2*)(C + (size_t)r0 * N + col) = v0;
                *(float2*)(C + (size_t)(r0 + 8) * N + col) = v1;
            } else {
                const int part = col >> 10;
                const int rem  = col & 1023;
                const int h = rem >> 6, d = rem & 63;
                float* dst = (part == 0) ? oQ : (part == 1) ? oK : oV;
#pragma unroll
                for (int half = 0; half < 2; half++) {
                    const int row = r0 + half * 8;
                    const int bb = row >> 10, s = row & 1023;
                    float2 v = make_float2(c[i][j][2 * half] + b0,
                                           c[i][j][2 * half + 1] + b1);
                    *(float2*)(dst + (size_t)(((bb * NHEAD + h) << 10) + s) * HD + d) = v;
                }
            }
        }
    }
}

// ---------------------------------------------------------------------------
// tf32-round a buffer (float4 per thread)
// ---------------------------------------------------------------------------
__global__ void cvt_tf32_kernel(const float4* __restrict__ in, float4* __restrict__ out)
{
    int i = blockIdx.x * blockDim.x + threadIdx.x;
    float4 v = in[i];
    v.x = tf32r(v.x); v.y = tf32r(v.y); v.z = tf32r(v.z); v.w = tf32r(v.w);
    out[i] = v;
}

// ---------------------------------------------------------------------------
// Gather mem rows from past_{q,k,v} + LayerNorm over D (tf32-rounded output)
// ---------------------------------------------------------------------------
__device__ __forceinline__ float blockReduceSum(float v, float* red)
{
    __syncthreads();
    int lane = threadIdx.x & 31, wid = threadIdx.x >> 5;
#pragma unroll
    for (int o = 16; o; o >>= 1) v += __shfl_xor_sync(0xffffffffu, v, o);
    if (lane == 0) red[wid] = v;
    __syncthreads();
    if (wid == 0) {
        v = (lane < 8) ? red[lane] : 0.f;
#pragma unroll
        for (int o = 4; o; o >>= 1) v += __shfl_xor_sync(0xffffffffu, v, o);
        if (lane == 0) red[0] = v;
    }
    __syncthreads();
    return red[0];
}

__global__ void mem_ln_kernel(const float* __restrict__ pq,
                              const float* __restrict__ pk,
                              const float* __restrict__ pv)
{
    __shared__ float red[32];
    int row = blockIdx.x;
    int j  = row % NMEM;
    int bs = row / NMEM;
    int s = bs & 1023, b = bs >> 10;
    int l = j & 3;
    const float* src = (j < 4) ? pq : (j < 8) ? pk : pv;
    size_t base = (size_t)(l * BATCH + b) * (NHEAD * S_LEN * HD) + (size_t)s * HD;

    int t = threadIdx.x;
    float vals[4];
    float sum = 0.f;
#pragma unroll
    for (int u = 0; u < 4; u++) {
        int c = t + (u << 8);
        int h = c >> 6, d = c & 63;
        float v = __ldg(src + base + (size_t)h * (S_LEN * HD) + d);
        vals[u] = v; sum += v;
    }
    sum = blockReduceSum(sum, red);
    float mean = sum * (1.f / 1024.f);
    float sq = 0.f;
#pragma unroll
    for (int u = 0; u < 4; u++) { float dv = vals[u] - mean; sq += dv * dv; }
    sq = blockReduceSum(sq, red);
    float inv = rsqrtf(sq * (1.f / 1024.f) + 1e-5f);

    float* orow = g_memln + (size_t)row * 1024;
#pragma unroll
    for (int u = 0; u < 4; u++) orow[t + (u << 8)] = tf32r((vals[u] - mean) * inv);
}

// ---------------------------------------------------------------------------
// Fused causal token attention + 12-slot memory attention (online softmax).
// ---------------------------------------------------------------------------
__global__ void __launch_bounds__(256, 2)
attn_kernel(const float* __restrict__ qg, const float* __restrict__ kg,
            const float* __restrict__ vg)
{
    __shared__ float ks[32][68];
    __shared__ float vs[32][68];
    __shared__ float ps[32][33];

    const int tid = threadIdx.x;
    const int tx = tid & 7;
    const int qi = tid >> 3;
    const int bh = blockIdx.y;
    const int b = bh >> 4, h = bh & 15;
    const int qt0 = blockIdx.x << 5;
    const int sq = qt0 + qi;
    const int c0 = tx << 3;

    float qreg[64];
    {
        const float4* qp = (const float4*)(qg + ((size_t)bh * 1024 + sq) * 64);
#pragma unroll
        for (int i = 0; i < 16; i++) ((float4*)qreg)[i] = __ldg(qp + i);
    }

    float m_i = -1e30f, l_i = 0.f;
    float acc[8];
#pragma unroll
    for (int i = 0; i < 8; i++) acc[i] = 0.f;

    const float* kbase = kg + (size_t)bh * 1024 * 64;
    const float* vbase = vg + (size_t)bh * 1024 * 64;

    for (int kt0 = 0; kt0 <= qt0; kt0 += 32) {
        __syncthreads();
        {
            const float4* kp = (const float4*)(kbase + (size_t)(kt0 + qi) * 64 + c0);
            const float4* vp = (const float4*)(vbase + (size_t)(kt0 + qi) * 64 + c0);
            float4 k0v = __ldg(kp), k1v = __ldg(kp + 1);
            float4 v0v = __ldg(vp), v1v = __ldg(vp + 1);
            *(float4*)&ks[qi][c0]     = k0v;
            *(float4*)&ks[qi][c0 + 4] = k1v;
            *(float4*)&vs[qi][c0]     = v0v;
            *(float4*)&vs[qi][c0 + 4] = v1v;
        }
        __syncthreads();

        float sc[4];
#pragma unroll
        for (int u = 0; u < 4; u++) {
            int kj = tx + (u << 3);
            float s = 0.f;
#pragma unroll
            for (int i = 0; i < 16; i++) {
                float4 kv = *(const float4*)&ks[kj][i << 2];
                s = fmaf(qreg[4 * i + 0], kv.x, s);
                s = fmaf(qreg[4 * i + 1], kv.y, s);
                s = fmaf(qreg[4 * i + 2], kv.z, s);
                s = fmaf(qreg[4 * i + 3], kv.w, s);
            }
            sc[u] = (kt0 + kj <= sq) ? s * SCALE : -1e30f;
        }
        float tmax = fmaxf(fmaxf(sc[0], sc[1]), fmaxf(sc[2], sc[3]));
#pragma unroll
        for (int o = 1; o < 8; o <<= 1)
            tmax = fmaxf(tmax, __shfl_xor_sync(0xffffffffu, tmax, o));
        float m_new = fmaxf(m_i, tmax);
        float corr = __expf(m_i - m_new);
        float psum = 0.f;
#pragma unroll
        for (int u = 0; u < 4; u++) {
            float p = __expf(sc[u] - m_new);
            ps[qi][tx + (u << 3)] = p;
            psum += p;
        }
#pragma unroll
        for (int o = 1; o < 8; o <<= 1)
            psum += __shfl_xor_sync(0xffffffffu, psum, o);
        l_i = l_i * corr + psum;
        m_i = m_new;
#pragma unroll
        for (int i = 0; i < 8; i++) acc[i] *= corr;
        __syncwarp();
#pragma unroll 8
        for (int kj = 0; kj < 32; kj++) {
            float p = ps[qi][kj];
            float4 v0 = *(const float4*)&vs[kj][c0];
            float4 v1 = *(const float4*)&vs[kj][c0 + 4];
            acc[0] = fmaf(p, v0.x, acc[0]);
            acc[1] = fmaf(p, v0.y, acc[1]);
            acc[2] = fmaf(p, v0.z, acc[2]);
            acc[3] = fmaf(p, v0.w, acc[3]);
            acc[4] = fmaf(p, v1.x, acc[4]);
            acc[5] = fmaf(p, v1.y, acc[5]);
            acc[6] = fmaf(p, v1.z, acc[6]);
            acc[7] = fmaf(p, v1.w, acc[7]);
        }
    }

    // ---------------- memory part (12 slots from g_rkv) ----------------
    const size_t rrow0 = (size_t)(b * 1024 + sq) * NMEM;
    const float* rkbase = g_rkv + rrow0 * 2048 + h * 64;

    float s0, s1 = -1e30f;
    {
        const float4* rp = (const float4*)(rkbase + (size_t)tx * 2048);
        float s = 0.f;
#pragma unroll
        for (int i = 0; i < 16; i++) {
            float4 kv = __ldg(rp + i);
            s = fmaf(qreg[4 * i + 0], kv.x, s);
            s = fmaf(qreg[4 * i + 1], kv.y, s);
            s = fmaf(qreg[4 * i + 2], kv.z, s);
            s = fmaf(qreg[4 * i + 3], kv.w, s);
        }
        s0 = s * SCALE;
    }
    if (tx < 4) {
        const float4* rp = (const float4*)(rkbase + (size_t)(tx + 8) * 2048);
        float s = 0.f;
#pragma unroll
        for (int i = 0; i < 16; i++) {
            float4 kv = __ldg(rp + i);
            s = fmaf(qreg[4 * i + 0], kv.x, s);
            s = fmaf(qreg[4 * i + 1], kv.y, s);
            s = fmaf(qreg[4 * i + 2], kv.z, s);
            s = fmaf(qreg[4 * i + 3], kv.w, s);
        }
        s1 = s * SCALE;
    }
    float tmax = fmaxf(s0, s1);
#pragma unroll
    for (int o = 1; o < 8; o <<= 1)
        tmax = fmaxf(tmax, __shfl_xor_sync(0xffffffffu, tmax, o));
    float m_new = fmaxf(m_i, tmax);
    float corr = __expf(m_i - m_new);

    __syncwarp();
    float p0 = __expf(s0 - m_new);
    ps[qi][tx] = p0;
    float psum = p0;
    if (tx < 4) {
        float p1 = __expf(s1 - m_new);
        ps[qi][tx + 8] = p1;
        psum += p1;
    }
#pragma unroll
    for (int o = 1; o < 8; o <<= 1)
        psum += __shfl_xor_sync(0xffffffffu, psum, o);
    l_i = l_i * corr + psum;
#pragma unroll
    for (int i = 0; i < 8; i++) acc[i] *= corr;
    __syncwarp();

    const float* rvbase = rkbase + 1024 + c0;
#pragma unroll
    for (int m = 0; m < NMEM; m++) {
        float p = ps[qi][m];
        const float4* rp = (const float4*)(rvbase + (size_t)m * 2048);
        float4 v0 = __ldg(rp), v1 = __ldg(rp + 1);
        acc[0] = fmaf(p, v0.x, acc[0]);
        acc[1] = fmaf(p, v0.y, acc[1]);
        acc[2] = fmaf(p, v0.z, acc[2]);
        acc[3] = fmaf(p, v0.w, acc[3]);
        acc[4] = fmaf(p, v1.x, acc[4]);
        acc[5] = fmaf(p, v1.y, acc[5]);
        acc[6] = fmaf(p, v1.z, acc[6]);
        acc[7] = fmaf(p, v1.w, acc[7]);
    }

    float inv = 1.f / l_i;
    float* op = g_merged + (size_t)(b * 1024 + sq) * 1024 + h * 64 + c0;
    float4 o0 = make_float4(tf32r(acc[0] * inv), tf32r(acc[1] * inv),
                            tf32r(acc[2] * inv), tf32r(acc[3] * inv));
    float4 o1 = make_float4(tf32r(acc[4] * inv), tf32r(acc[5] * inv),
                            tf32r(acc[6] * inv), tf32r(acc[7] * inv));
    *(float4*)op = o0;
    *((float4*)op + 1) = o1;
}

// ---------------------------------------------------------------------------
// launch
// ---------------------------------------------------------------------------
extern "C" void kernel_launch(void* const* d_in, const int* in_sizes, int n_in,
                              void* d_out, int out_size)
{
    const float* x     = (const float*)d_in[0];
    const float* pastk = (const float*)d_in[1];
    const float* pastv = (const float*)d_in[2];
    const float* pastq = (const float*)d_in[3];
    const float* Wqkv  = (const float*)d_in[4];
    const float* bqkv  = (const float*)d_in[5];
    const float* Wout  = (const float*)d_in[6];
    const float* bout  = (const float*)d_in[7];

    float* out = (float*)d_out;                 // (B,S,D)
    float* oK  = out + (size_t)2097152;         // (B,H,S,hd)
    float* oV  = out + (size_t)2 * 2097152;
    float* oQ  = out + (size_t)3 * 2097152;

    static float* s_memln = nullptr;
    static float* s_rkv = nullptr;
    static float* s_merged = nullptr;
    static float* s_xr = nullptr;
    static float* s_wqkv = nullptr;
    static float* s_wout = nullptr;
    if (!s_memln) {
        cudaGetSymbolAddress((void**)&s_memln, g_memln);
        cudaGetSymbolAddress((void**)&s_rkv, g_rkv);
        cudaGetSymbolAddress((void**)&s_merged, g_merged);
        cudaGetSymbolAddress((void**)&s_xr, g_xr);
        cudaGetSymbolAddress((void**)&s_wqkv, g_wqkv);
        cudaGetSymbolAddress((void**)&s_wout, g_wout);
        cudaFuncSetAttribute(gemm_big<0>, cudaFuncAttributeMaxDynamicSharedMemorySize,
                             GB_SMEM);
        cudaFuncSetAttribute(gemm_big<1>, cudaFuncAttributeMaxDynamicSharedMemorySize,
                             GB_SMEM);
    }

    // 0) tf32-round GEMM operands
    cvt_tf32_kernel<<<2048, 256>>>((const float4*)x,    (float4*)s_xr);
    cvt_tf32_kernel<<<3072, 256>>>((const float4*)Wqkv, (float4*)s_wqkv);
    cvt_tf32_kernel<<<1024, 256>>>((const float4*)Wout, (float4*)s_wout);

    // 1) qkv projection (tensor core tf32, big tile), scatter q/k/v
    {
        dim3 g(3072 / 128, 2048 / 256);
        gemm_big<1><<<g, 256, GB_SMEM>>>(s_xr, s_wqkv, bqkv, nullptr,
                                         2048, 3072, 1024, oQ, oK, oV);
    }
    // 2) mem gather + LayerNorm (tf32-rounded output)
    mem_ln_kernel<<<24576, 256>>>(pastq, pastk, pastv);
    // 3) rk/rv projection (tensor core tf32, big tile)
    {
        dim3 g(2048 / 128, 24576 / 256);
        gemm_big<0><<<g, 256, GB_SMEM>>>(s_memln, s_wqkv + (size_t)1024 * 1024,
                                         bqkv + 1024, s_rkv, 24576, 2048, 1024,
                                         nullptr, nullptr, nullptr);
    }
    // 4) fused attention (token causal + memory slots)
    {
        dim3 g(1024 / 32, BATCH * NHEAD);
        attn_kernel<<<g, 256>>>(oQ, oK, oV);
    }
    // 5) output projection (128x128 kernel: better wave fill at small grid)
    {
        dim3 g(1024 / 128, 2048 / 128);
        gemm_tf32<0><<<g, 256>>>(s_merged, s_wout, bout, out, 2048, 1024, 1024,
                                 nullptr, nullptr, nullptr);
    }
}

// round 6
// speedup vs baseline: 3.7971x; 1.3383x over previous
#include <cuda_runtime.h>
#include <cuda_fp16.h>
#include <cstdint>

// Problem constants
#define BATCH   2
#define S_LEN   1024
#define D_DIM   1024
#define NHEAD   16
#define HD      64
#define NMEM    12          // 3*L
#define SCALE   0.125f      // 1/sqrt(64)

// ---------------------------------------------------------------------------
// Scratch (device globals: allocation-free)
// ---------------------------------------------------------------------------
__device__ __align__(16) __half g_memlnh[(size_t)24576 * 1024]; // LN'd mem rows (fp16)
__device__ __align__(16) __half g_xh    [(size_t)2048 * 1024];  // fp16 x
__device__ __align__(16) __half g_wqkvh [(size_t)3072 * 1024];  // fp16 Wqkv
__device__ float g_rkv  [(size_t)24576 * 2048];  // (B*S*M, 2D): [0,1024)=rk, [1024,2048)=rv
__device__ float g_merged[(size_t)2048 * 1024];  // (B*S, D) attn out (tf32-rounded)
__device__ float g_wout [(size_t)1024 * 1024];   // tf32-rounded Wout

// ---------------------------------------------------------------------------
// Helpers
// ---------------------------------------------------------------------------
__device__ __forceinline__ uint32_t smem_u32(const void* p) {
    uint32_t a;
    asm("{ .reg .u64 t; cvta.to.shared.u64 t, %1; cvt.u32.u64 %0, t; }" : "=r"(a) : "l"(p));
    return a;
}
__device__ __forceinline__ float tf32r(float x) {
    uint32_t u;
    asm("cvt.rna.tf32.f32 %0, %1;" : "=r"(u) : "f"(x));
    return __uint_as_float(u);
}
__device__ __forceinline__ void cp16(uint32_t dst, const void* src) {
    asm volatile("cp.async.cg.shared.global [%0], [%1], 16;" :: "r"(dst), "l"(src));
}
__device__ __forceinline__ void ldsm4(uint32_t* r, uint32_t addr) {
    asm volatile("ldmatrix.sync.aligned.m8n8.x4.shared.b16 {%0,%1,%2,%3}, [%4];"
                 : "=r"(r[0]), "=r"(r[1]), "=r"(r[2]), "=r"(r[3]) : "r"(addr));
}
__device__ __forceinline__ void mma8(float* c, const uint32_t* a, const uint32_t* b) {
    asm volatile("mma.sync.aligned.m16n8k8.row.col.f32.tf32.tf32.f32 "
                 "{%0,%1,%2,%3}, {%4,%5,%6,%7}, {%8,%9}, {%0,%1,%2,%3};"
                 : "+f"(c[0]), "+f"(c[1]), "+f"(c[2]), "+f"(c[3])
                 : "r"(a[0]), "r"(a[1]), "r"(a[2]), "r"(a[3]), "r"(b[0]), "r"(b[1]));
}
__device__ __forceinline__ void mma16(float* c, const uint32_t* a, const uint32_t* b) {
    asm volatile("mma.sync.aligned.m16n8k16.row.col.f32.f16.f16.f32 "
                 "{%0,%1,%2,%3}, {%4,%5,%6,%7}, {%8,%9}, {%0,%1,%2,%3};"
                 : "+f"(c[0]), "+f"(c[1]), "+f"(c[2]), "+f"(c[3])
                 : "r"(a[0]), "r"(a[1]), "r"(a[2]), "r"(a[3]), "r"(b[0]), "r"(b[1]));
}

// ===========================================================================
// fp16 GEMM (NT): C[m,n] = sum_k A[m,k]*B[n,k] + bias[n]   (fp32 accumulate)
// Block tile 256x128, BK=64 halves, 3-stage cp.async, 256 thr (8 warps 4x2),
// warp tile 64x64 = 4 m16 x 8 n8 subtiles of m16n8k16.
// Row stride 72 halves (144B): ldmatrix 8-row phases hit distinct banks.
// EPI==0: row-major store. EPI==1: qkv scatter.
// ===========================================================================
#define GF_ASTG 36864u   // 256*72*2 bytes per A stage
#define GF_BSTG 18432u   // 128*72*2 bytes per B stage
#define GF_SMEM 165888

template<int EPI>
__global__ void __launch_bounds__(256, 1)
gemm_fp16(const __half* __restrict__ A, const __half* __restrict__ B,
          const float* __restrict__ bias, float* __restrict__ C,
          int M, int N, int K,
          float* __restrict__ oQ, float* __restrict__ oK, float* __restrict__ oV)
{
    extern __shared__ char smemc[];
    const uint32_t aBase = smem_u32(smemc);
    const uint32_t bBase = aBase + 3u * GF_ASTG;

    const int tid = threadIdx.x;
    const int lane = tid & 31, wid = tid >> 5;
    const int m0 = blockIdx.y << 8;
    const int n0 = blockIdx.x << 7;
    const int wm = (wid & 3) << 6;
    const int wn = (wid >> 2) << 6;

    // global->smem: thread covers one 16B seg (8 halves) in rows {grow + 32p}
    const int grow = tid >> 3;
    const int gc8  = (tid & 7) << 3;         // half offset within 64-half row
    const __half* Ag = A + (size_t)(m0 + grow) * K + gc8;
    const __half* Bg = B + (size_t)(n0 + grow) * K + gc8;
    const uint32_t sOff = (uint32_t)((grow * 72 + gc8) << 1);

    // ldmatrix address components
    const int rA = lane & 15, cA = (lane >> 4) << 3;              // A 16x16 tiles
    const int rB = (lane & 7) + ((lane >> 4) << 3);               // B n-rows
    const int cB = ((lane >> 3) & 1) << 3;                        // B k-half sel

#define GF_LOAD(stage, kb) do {                                                \
    const __half* _a = Ag + ((kb) << 6);                                       \
    const __half* _b = Bg + ((kb) << 6);                                       \
    const uint32_t _da = aBase + (uint32_t)(stage) * GF_ASTG + sOff;           \
    const uint32_t _db = bBase + (uint32_t)(stage) * GF_BSTG + sOff;           \
    _Pragma("unroll")                                                          \
    for (int _p = 0; _p < 8; _p++)                                             \
        cp16(_da + (uint32_t)_p * 4608u, _a + (size_t)(_p << 5) * K);          \
    _Pragma("unroll")                                                          \
    for (int _p = 0; _p < 4; _p++)                                             \
        cp16(_db + (uint32_t)_p * 4608u, _b + (size_t)(_p << 5) * K);          \
    asm volatile("cp.async.commit_group;" ::: "memory");                       \
} while (0)

    float c[4][8][4];
#pragma unroll
    for (int i = 0; i < 4; i++)
#pragma unroll
        for (int j = 0; j < 8; j++)
#pragma unroll
            for (int r = 0; r < 4; r++) c[i][j][r] = 0.f;

    const int NK = K >> 6;                   // 64-half K stages
    GF_LOAD(0, 0);
    GF_LOAD(1, 1);

    for (int kb = 0; kb < NK; ++kb) {
        if (kb < NK - 1)
            asm volatile("cp.async.wait_group 1;" ::: "memory");
        else
            asm volatile("cp.async.wait_group 0;" ::: "memory");
        __syncthreads();

        if (kb + 2 < NK) {
            int ns = kb + 2; ns = ns - (ns / 3) * 3;
            GF_LOAD(ns, kb + 2);
        }

        int st = kb - (kb / 3) * 3;
        const uint32_t aS = aBase + (uint32_t)st * GF_ASTG;
        const uint32_t bS = bBase + (uint32_t)st * GF_BSTG;

#pragma unroll
        for (int ks = 0; ks < 4; ++ks) {
            uint32_t a[4][4];
#pragma unroll
            for (int i = 0; i < 4; i++)
                ldsm4(a[i], aS + (uint32_t)(((wm + i * 16 + rA) * 72 + cA + ks * 16) << 1));
            uint32_t b[8][2];
#pragma unroll
            for (int j2 = 0; j2 < 4; j2++) {
                uint32_t r4[4];
                ldsm4(r4, bS + (uint32_t)(((wn + j2 * 16 + rB) * 72 + cB + ks * 16) << 1));
                b[2 * j2 + 0][0] = r4[0]; b[2 * j2 + 0][1] = r4[1];
                b[2 * j2 + 1][0] = r4[2]; b[2 * j2 + 1][1] = r4[3];
            }
#pragma unroll
            for (int i = 0; i < 4; i++)
#pragma unroll
                for (int j = 0; j < 8; j++)
                    mma16(c[i][j], a[i], b[j]);
        }
    }
#undef GF_LOAD

    // epilogue (fragment layout identical to k8 path)
    const int gro = lane >> 2;
    const int gco = (lane & 3) << 1;
#pragma unroll
    for (int i = 0; i < 4; i++) {
        const int r0 = m0 + wm + i * 16 + gro;
#pragma unroll
        for (int j = 0; j < 8; j++) {
            const int col = n0 + wn + j * 8 + gco;
            const float b0 = bias[col], b1 = bias[col + 1];
            if (EPI == 0) {
                float2 v0 = make_float2(c[i][j][0] + b0, c[i][j][1] + b1);
                float2 v1 = make_float2(c[i][j][2] + b0, c[i][j][3] + b1);
                *(float2*)(C + (size_t)r0 * N + col) = v0;
                *(float2*)(C + (size_t)(r0 + 8) * N + col) = v1;
            } else {
                const int part = col >> 10;
                const int rem  = col & 1023;
                const int h = rem >> 6, d = rem & 63;
                float* dst = (part == 0) ? oQ : (part == 1) ? oK : oV;
#pragma unroll
                for (int half = 0; half < 2; half++) {
                    const int row = r0 + half * 8;
                    const int bb = row >> 10, s = row & 1023;
                    float2 v = make_float2(c[i][j][2 * half] + b0,
                                           c[i][j][2 * half + 1] + b1);
                    *(float2*)(dst + (size_t)(((bb * NHEAD + h) << 10) + s) * HD + d) = v;
                }
            }
        }
    }
}

// ---------------------------------------------------------------------------
// 128x128 tf32 GEMM (round-4 proven) — GEMM3 (small grid)
// ---------------------------------------------------------------------------
__global__ void __launch_bounds__(256)
gemm_tf32(const float* __restrict__ A, const float* __restrict__ B,
          const float* __restrict__ bias, float* __restrict__ C,
          int M, int N, int K)
{
    __shared__ float sA[2][128][20];
    __shared__ float sB[2][128][20];

    const int tid = threadIdx.x;
    const int lane = tid & 31, wid = tid >> 5;
    const int m0 = blockIdx.y << 7, n0 = blockIdx.x << 7;
    const int wm = (wid & 1) << 6;
    const int wn = (wid >> 1) << 5;

    const int grow = tid >> 1;
    const int gseg = (tid & 1) << 1;
    const float* Ag = A + (size_t)(m0 + grow) * K + (gseg << 2);
    const float* Bg = B + (size_t)(n0 + grow) * K + (gseg << 2);
    const uint32_t sOffLd = (uint32_t)(grow * 80 + (gseg << 4));

    const int tIn = lane & 7, sel = lane >> 3;
    const int rAl = tIn + ((sel & 1) << 3);
    const int cAl = (sel & 2) << 1;
    const int rBl = tIn + ((sel & 2) << 2);
    const int cBl = (sel & 1) << 2;

    const uint32_t aBase = smem_u32(&sA[0][0][0]);
    const uint32_t bBase = smem_u32(&sB[0][0][0]);

#define G_LOAD(slot, kblk) do {                                                \
    const float* _a = Ag + ((kblk) << 4);                                      \
    const float* _b = Bg + ((kblk) << 4);                                      \
    uint32_t _da = aBase + (uint32_t)(slot) * 10240u + sOffLd;                 \
    uint32_t _db = bBase + (uint32_t)(slot) * 10240u + sOffLd;                 \
    cp16(_da, _a); cp16(_da + 16, _a + 4);                                     \
    cp16(_db, _b); cp16(_db + 16, _b + 4);                                     \
    asm volatile("cp.async.commit_group;" ::: "memory");                       \
} while (0)

    float c[4][4][4];
#pragma unroll
    for (int i = 0; i < 4; i++)
#pragma unroll
        for (int j = 0; j < 4; j++)
#pragma unroll
            for (int r = 0; r < 4; r++) c[i][j][r] = 0.f;

    const int kIters = K >> 4;
    G_LOAD(0, 0);
    G_LOAD(1, 1);

    for (int it = 0; it < kIters; ++it) {
        if (it + 2 < kIters)
            asm volatile("cp.async.wait_group 1;" ::: "memory");
        else
            asm volatile("cp.async.wait_group 0;" ::: "memory");
        __syncthreads();

        const int st = it & 1;
        const uint32_t aS = aBase + (uint32_t)st * 10240u;
        const uint32_t bS = bBase + (uint32_t)st * 10240u;

#pragma unroll
        for (int ks = 0; ks < 2; ++ks) {
            uint32_t a[4][4];
#pragma unroll
            for (int i = 0; i < 4; i++) {
                uint32_t ad = aS + (uint32_t)(((wm + i * 16 + rAl) * 20 + ks * 8 + cAl) << 2);
                ldsm4(a[i], ad);
            }
            uint32_t b[4][2];
#pragma unroll
            for (int j2 = 0; j2 < 2; j2++) {
                uint32_t r4[4];
                uint32_t bd = bS + (uint32_t)(((wn + j2 * 16 + rBl) * 20 + ks * 8 + cBl) << 2);
                ldsm4(r4, bd);
                b[2 * j2 + 0][0] = r4[0]; b[2 * j2 + 0][1] = r4[1];
                b[2 * j2 + 1][0] = r4[2]; b[2 * j2 + 1][1] = r4[3];
            }
#pragma unroll
            for (int i = 0; i < 4; i++)
#pragma unroll
                for (int j = 0; j < 4; j++)
                    mma8(c[i][j], a[i], b[j]);
        }
        __syncthreads();
        if (it + 2 < kIters) G_LOAD(st, it + 2);
    }
#undef G_LOAD

    const int gro = lane >> 2;
    const int gco = (lane & 3) << 1;
#pragma unroll
    for (int i = 0; i < 4; i++) {
        const int r0 = m0 + wm + i * 16 + gro;
#pragma unroll
        for (int j = 0; j < 4; j++) {
            const int col = n0 + wn + j * 8 + gco;
            const float b0 = bias[col], b1 = bias[col + 1];
            float2 v0 = make_float2(c[i][j][0] + b0, c[i][j][1] + b1);
            float2 v1 = make_float2(c[i][j][2] + b0, c[i][j][3] + b1);
            *(float2*)(C + (size_t)r0 * N + col) = v0;
            *(float2*)(C + (size_t)(r0 + 8) * N + col) = v1;
        }
    }
}

// ---------------------------------------------------------------------------
// conversion kernels
// ---------------------------------------------------------------------------
__global__ void cvt_fp16_kernel(const float4* __restrict__ in, __half2* __restrict__ out)
{
    int i = blockIdx.x * blockDim.x + threadIdx.x;
    float4 v = in[i];
    out[2 * i + 0] = __floats2half2_rn(v.x, v.y);
    out[2 * i + 1] = __floats2half2_rn(v.z, v.w);
}
__global__ void cvt_tf32_kernel(const float4* __restrict__ in, float4* __restrict__ out)
{
    int i = blockIdx.x * blockDim.x + threadIdx.x;
    float4 v = in[i];
    v.x = tf32r(v.x); v.y = tf32r(v.y); v.z = tf32r(v.z); v.w = tf32r(v.w);
    out[i] = v;
}

// ---------------------------------------------------------------------------
// Gather mem rows from past_{q,k,v} + LayerNorm over D -> fp16 output
// ---------------------------------------------------------------------------
__device__ __forceinline__ float blockReduceSum(float v, float* red)
{
    __syncthreads();
    int lane = threadIdx.x & 31, wid = threadIdx.x >> 5;
#pragma unroll
    for (int o = 16; o; o >>= 1) v += __shfl_xor_sync(0xffffffffu, v, o);
    if (lane == 0) red[wid] = v;
    __syncthreads();
    if (wid == 0) {
        v = (lane < 8) ? red[lane] : 0.f;
#pragma unroll
        for (int o = 4; o; o >>= 1) v += __shfl_xor_sync(0xffffffffu, v, o);
        if (lane == 0) red[0] = v;
    }
    __syncthreads();
    return red[0];
}

__global__ void mem_ln_kernel(const float* __restrict__ pq,
                              const float* __restrict__ pk,
                              const float* __restrict__ pv)
{
    __shared__ float red[32];
    int row = blockIdx.x;
    int j  = row % NMEM;
    int bs = row / NMEM;
    int s = bs & 1023, b = bs >> 10;
    int l = j & 3;
    const float* src = (j < 4) ? pq : (j < 8) ? pk : pv;
    size_t base = (size_t)(l * BATCH + b) * (NHEAD * S_LEN * HD) + (size_t)s * HD;

    int t = threadIdx.x;
    float vals[4];
    float sum = 0.f;
#pragma unroll
    for (int u = 0; u < 4; u++) {
        int c = t + (u << 8);
        int h = c >> 6, d = c & 63;
        float v = __ldg(src + base + (size_t)h * (S_LEN * HD) + d);
        vals[u] = v; sum += v;
    }
    sum = blockReduceSum(sum, red);
    float mean = sum * (1.f / 1024.f);
    float sq = 0.f;
#pragma unroll
    for (int u = 0; u < 4; u++) { float dv = vals[u] - mean; sq += dv * dv; }
    sq = blockReduceSum(sq, red);
    float inv = rsqrtf(sq * (1.f / 1024.f) + 1e-5f);

    __half* orow = g_memlnh + (size_t)row * 1024;
#pragma unroll
    for (int u = 0; u < 4; u++)
        orow[t + (u << 8)] = __float2half_rn((vals[u] - mean) * inv);
}

// ---------------------------------------------------------------------------
// Fused causal token attention + 12-slot memory attention (online softmax).
// ---------------------------------------------------------------------------
__global__ void __launch_bounds__(256, 2)
attn_kernel(const float* __restrict__ qg, const float* __restrict__ kg,
            const float* __restrict__ vg)
{
    __shared__ float ks[32][68];
    __shared__ float vs[32][68];
    __shared__ float ps[32][33];

    const int tid = threadIdx.x;
    const int tx = tid & 7;
    const int qi = tid >> 3;
    const int bh = blockIdx.y;
    const int b = bh >> 4, h = bh & 15;
    const int qt0 = blockIdx.x << 5;
    const int sq = qt0 + qi;
    const int c0 = tx << 3;

    float qreg[64];
    {
        const float4* qp = (const float4*)(qg + ((size_t)bh * 1024 + sq) * 64);
#pragma unroll
        for (int i = 0; i < 16; i++) ((float4*)qreg)[i] = __ldg(qp + i);
    }

    float m_i = -1e30f, l_i = 0.f;
    float acc[8];
#pragma unroll
    for (int i = 0; i < 8; i++) acc[i] = 0.f;

    const float* kbase = kg + (size_t)bh * 1024 * 64;
    const float* vbase = vg + (size_t)bh * 1024 * 64;

    for (int kt0 = 0; kt0 <= qt0; kt0 += 32) {
        __syncthreads();
        {
            const float4* kp = (const float4*)(kbase + (size_t)(kt0 + qi) * 64 + c0);
            const float4* vp = (const float4*)(vbase + (size_t)(kt0 + qi) * 64 + c0);
            float4 k0v = __ldg(kp), k1v = __ldg(kp + 1);
            float4 v0v = __ldg(vp), v1v = __ldg(vp + 1);
            *(float4*)&ks[qi][c0]     = k0v;
            *(float4*)&ks[qi][c0 + 4] = k1v;
            *(float4*)&vs[qi][c0]     = v0v;
            *(float4*)&vs[qi][c0 + 4] = v1v;
        }
        __syncthreads();

        float sc[4];
#pragma unroll
        for (int u = 0; u < 4; u++) {
            int kj = tx + (u << 3);
            float s = 0.f;
#pragma unroll
            for (int i = 0; i < 16; i++) {
                float4 kv = *(const float4*)&ks[kj][i << 2];
                s = fmaf(qreg[4 * i + 0], kv.x, s);
                s = fmaf(qreg[4 * i + 1], kv.y, s);
                s = fmaf(qreg[4 * i + 2], kv.z, s);
                s = fmaf(qreg[4 * i + 3], kv.w, s);
            }
            sc[u] = (kt0 + kj <= sq) ? s * SCALE : -1e30f;
        }
        float tmax = fmaxf(fmaxf(sc[0], sc[1]), fmaxf(sc[2], sc[3]));
#pragma unroll
        for (int o = 1; o < 8; o <<= 1)
            tmax = fmaxf(tmax, __shfl_xor_sync(0xffffffffu, tmax, o));
        float m_new = fmaxf(m_i, tmax);
        float corr = __expf(m_i - m_new);
        float psum = 0.f;
#pragma unroll
        for (int u = 0; u < 4; u++) {
            float p = __expf(sc[u] - m_new);
            ps[qi][tx + (u << 3)] = p;
            psum += p;
        }
#pragma unroll
        for (int o = 1; o < 8; o <<= 1)
            psum += __shfl_xor_sync(0xffffffffu, psum, o);
        l_i = l_i * corr + psum;
        m_i = m_new;
#pragma unroll
        for (int i = 0; i < 8; i++) acc[i] *= corr;
        __syncwarp();
#pragma unroll 8
        for (int kj = 0; kj < 32; kj++) {
            float p = ps[qi][kj];
            float4 v0 = *(const float4*)&vs[kj][c0];
            float4 v1 = *(const float4*)&vs[kj][c0 + 4];
            acc[0] = fmaf(p, v0.x, acc[0]);
            acc[1] = fmaf(p, v0.y, acc[1]);
            acc[2] = fmaf(p, v0.z, acc[2]);
            acc[3] = fmaf(p, v0.w, acc[3]);
            acc[4] = fmaf(p, v1.x, acc[4]);
            acc[5] = fmaf(p, v1.y, acc[5]);
            acc[6] = fmaf(p, v1.z, acc[6]);
            acc[7] = fmaf(p, v1.w, acc[7]);
        }
    }

    // ---------------- memory part (12 slots from g_rkv) ----------------
    const size_t rrow0 = (size_t)(b * 1024 + sq) * NMEM;
    const float* rkbase = g_rkv + rrow0 * 2048 + h * 64;

    float s0, s1 = -1e30f;
    {
        const float4* rp = (const float4*)(rkbase + (size_t)tx * 2048);
        float s = 0.f;
#pragma unroll
        for (int i = 0; i < 16; i++) {
            float4 kv = __ldg(rp + i);
            s = fmaf(qreg[4 * i + 0], kv.x, s);
            s = fmaf(qreg[4 * i + 1], kv.y, s);
            s = fmaf(qreg[4 * i + 2], kv.z, s);
            s = fmaf(qreg[4 * i + 3], kv.w, s);
        }
        s0 = s * SCALE;
    }
    if (tx < 4) {
        const float4* rp = (const float4*)(rkbase + (size_t)(tx + 8) * 2048);
        float s = 0.f;
#pragma unroll
        for (int i = 0; i < 16; i++) {
            float4 kv = __ldg(rp + i);
            s = fmaf(qreg[4 * i + 0], kv.x, s);
            s = fmaf(qreg[4 * i + 1], kv.y, s);
            s = fmaf(qreg[4 * i + 2], kv.z, s);
            s = fmaf(qreg[4 * i + 3], kv.w, s);
        }
        s1 = s * SCALE;
    }
    float tmax = fmaxf(s0, s1);
#pragma unroll
    for (int o = 1; o < 8; o <<= 1)
        tmax = fmaxf(tmax, __shfl_xor_sync(0xffffffffu, tmax, o));
    float m_new = fmaxf(m_i, tmax);
    float corr = __expf(m_i - m_new);

    __syncwarp();
    float p0 = __expf(s0 - m_new);
    ps[qi][tx] = p0;
    float psum = p0;
    if (tx < 4) {
        float p1 = __expf(s1 - m_new);
        ps[qi][tx + 8] = p1;
        psum += p1;
    }
#pragma unroll
    for (int o = 1; o < 8; o <<= 1)
        psum += __shfl_xor_sync(0xffffffffu, psum, o);
    l_i = l_i * corr + psum;
#pragma unroll
    for (int i = 0; i < 8; i++) acc[i] *= corr;
    __syncwarp();

    const float* rvbase = rkbase + 1024 + c0;
#pragma unroll
    for (int m = 0; m < NMEM; m++) {
        float p = ps[qi][m];
        const float4* rp = (const float4*)(rvbase + (size_t)m * 2048);
        float4 v0 = __ldg(rp), v1 = __ldg(rp + 1);
        acc[0] = fmaf(p, v0.x, acc[0]);
        acc[1] = fmaf(p, v0.y, acc[1]);
        acc[2] = fmaf(p, v0.z, acc[2]);
        acc[3] = fmaf(p, v0.w, acc[3]);
        acc[4] = fmaf(p, v1.x, acc[4]);
        acc[5] = fmaf(p, v1.y, acc[5]);
        acc[6] = fmaf(p, v1.z, acc[6]);
        acc[7] = fmaf(p, v1.w, acc[7]);
    }

    float inv = 1.f / l_i;
    float* op = g_merged + (size_t)(b * 1024 + sq) * 1024 + h * 64 + c0;
    float4 o0 = make_float4(tf32r(acc[0] * inv), tf32r(acc[1] * inv),
                            tf32r(acc[2] * inv), tf32r(acc[3] * inv));
    float4 o1 = make_float4(tf32r(acc[4] * inv), tf32r(acc[5] * inv),
                            tf32r(acc[6] * inv), tf32r(acc[7] * inv));
    *(float4*)op = o0;
    *((float4*)op + 1) = o1;
}

// ---------------------------------------------------------------------------
// launch
// ---------------------------------------------------------------------------
extern "C" void kernel_launch(void* const* d_in, const int* in_sizes, int n_in,
                              void* d_out, int out_size)
{
    const float* x     = (const float*)d_in[0];
    const float* pastk = (const float*)d_in[1];
    const float* pastv = (const float*)d_in[2];
    const float* pastq = (const float*)d_in[3];
    const float* Wqkv  = (const float*)d_in[4];
    const float* bqkv  = (const float*)d_in[5];
    const float* Wout  = (const float*)d_in[6];
    const float* bout  = (const float*)d_in[7];

    float* out = (float*)d_out;                 // (B,S,D)
    float* oK  = out + (size_t)2097152;         // (B,H,S,hd)
    float* oV  = out + (size_t)2 * 2097152;
    float* oQ  = out + (size_t)3 * 2097152;

    static __half* s_memlnh = nullptr;
    static __half* s_xh = nullptr;
    static __half* s_wqkvh = nullptr;
    static float* s_rkv = nullptr;
    static float* s_merged = nullptr;
    static float* s_wout = nullptr;
    if (!s_memlnh) {
        cudaGetSymbolAddress((void**)&s_memlnh, g_memlnh);
        cudaGetSymbolAddress((void**)&s_xh, g_xh);
        cudaGetSymbolAddress((void**)&s_wqkvh, g_wqkvh);
        cudaGetSymbolAddress((void**)&s_rkv, g_rkv);
        cudaGetSymbolAddress((void**)&s_merged, g_merged);
        cudaGetSymbolAddress((void**)&s_wout, g_wout);
        cudaFuncSetAttribute(gemm_fp16<0>, cudaFuncAttributeMaxDynamicSharedMemorySize,
                             GF_SMEM);
        cudaFuncSetAttribute(gemm_fp16<1>, cudaFuncAttributeMaxDynamicSharedMemorySize,
                             GF_SMEM);
    }

    // 0) convert operands: x/Wqkv -> fp16; Wout -> tf32-rounded fp32
    cvt_fp16_kernel<<<2048, 256>>>((const float4*)x,    (__half2*)s_xh);
    cvt_fp16_kernel<<<3072, 256>>>((const float4*)Wqkv, (__half2*)s_wqkvh);
    cvt_tf32_kernel<<<1024, 256>>>((const float4*)Wout, (float4*)s_wout);

    // 1) qkv projection (fp16 tensor core), scatter q/k/v into output regions
    {
        dim3 g(3072 / 128, 2048 / 256);
        gemm_fp16<1><<<g, 256, GF_SMEM>>>(s_xh, s_wqkvh, bqkv, nullptr,
                                          2048, 3072, 1024, oQ, oK, oV);
    }
    // 2) mem gather + LayerNorm -> fp16
    mem_ln_kernel<<<24576, 256>>>(pastq, pastk, pastv);
    // 3) rk/rv projection (fp16 tensor core)
    {
        dim3 g(2048 / 128, 24576 / 256);
        gemm_fp16<0><<<g, 256, GF_SMEM>>>(s_memlnh, s_wqkvh + (size_t)1024 * 1024,
                                          bqkv + 1024, s_rkv, 24576, 2048, 1024,
                                          nullptr, nullptr, nullptr);
    }
    // 4) fused attention (token causal + memory slots)
    {
        dim3 g(1024 / 32, BATCH * NHEAD);
        attn_kernel<<<g, 256>>>(oQ, oK, oV);
    }
    // 5) output projection (tf32, 128x128: better wave fill at small grid)
    {
        dim3 g(1024 / 128, 2048 / 128);
        gemm_tf32<<<g, 256>>>(s_merged, s_wout, bout, out, 2048, 1024, 1024);
    }
}

// round 7
// speedup vs baseline: 6.7981x; 1.7903x over previous
#include <cuda_runtime.h>
#include <cuda_fp16.h>
#include <cstdint>

// Problem constants
#define BATCH   2
#define S_LEN   1024
#define D_DIM   1024
#define NHEAD   16
#define HD      64
#define NMEM    12          // 3*L
#define SCALE   0.125f      // 1/sqrt(64)

// ---------------------------------------------------------------------------
// Scratch (device globals: allocation-free)
// ---------------------------------------------------------------------------
__device__ __align__(16) __half g_memlnh[(size_t)24576 * 1024]; // LN'd mem rows (fp16)
__device__ __align__(16) __half g_xh    [(size_t)2048 * 1024];  // fp16 x
__device__ __align__(16) __half g_wqkvh [(size_t)3072 * 1024];  // fp16 Wqkv
__device__ __align__(16) __half g_qhh   [(size_t)2048 * 1024];  // fp16 q (B,H,S,hd)
__device__ __align__(16) __half g_khh   [(size_t)2048 * 1024];  // fp16 k
__device__ __align__(16) __half g_vhh   [(size_t)2048 * 1024];  // fp16 v
__device__ float g_rkv  [(size_t)24576 * 2048];  // (B*S*M, 2D): [0,1024)=rk, [1024,2048)=rv
__device__ float g_merged[(size_t)2048 * 1024];  // (B*S, D) attn out (tf32-rounded)
__device__ float g_wout [(size_t)1024 * 1024];   // tf32-rounded Wout

// ---------------------------------------------------------------------------
// Helpers
// ---------------------------------------------------------------------------
__device__ __forceinline__ uint32_t smem_u32(const void* p) {
    uint32_t a;
    asm("{ .reg .u64 t; cvta.to.shared.u64 t, %1; cvt.u32.u64 %0, t; }" : "=r"(a) : "l"(p));
    return a;
}
__device__ __forceinline__ float tf32r(float x) {
    uint32_t u;
    asm("cvt.rna.tf32.f32 %0, %1;" : "=r"(u) : "f"(x));
    return __uint_as_float(u);
}
__device__ __forceinline__ void cp16(uint32_t dst, const void* src) {
    asm volatile("cp.async.cg.shared.global [%0], [%1], 16;" :: "r"(dst), "l"(src));
}
__device__ __forceinline__ void ldsm4(uint32_t* r, uint32_t addr) {
    asm volatile("ldmatrix.sync.aligned.m8n8.x4.shared.b16 {%0,%1,%2,%3}, [%4];"
                 : "=r"(r[0]), "=r"(r[1]), "=r"(r[2]), "=r"(r[3]) : "r"(addr));
}
__device__ __forceinline__ void ldsm4t(uint32_t* r, uint32_t addr) {
    asm volatile("ldmatrix.sync.aligned.m8n8.x4.trans.shared.b16 {%0,%1,%2,%3}, [%4];"
                 : "=r"(r[0]), "=r"(r[1]), "=r"(r[2]), "=r"(r[3]) : "r"(addr));
}
__device__ __forceinline__ void mma8(float* c, const uint32_t* a, const uint32_t* b) {
    asm volatile("mma.sync.aligned.m16n8k8.row.col.f32.tf32.tf32.f32 "
                 "{%0,%1,%2,%3}, {%4,%5,%6,%7}, {%8,%9}, {%0,%1,%2,%3};"
                 : "+f"(c[0]), "+f"(c[1]), "+f"(c[2]), "+f"(c[3])
                 : "r"(a[0]), "r"(a[1]), "r"(a[2]), "r"(a[3]), "r"(b[0]), "r"(b[1]));
}
__device__ __forceinline__ void mma16(float* c, const uint32_t* a, const uint32_t* b) {
    asm volatile("mma.sync.aligned.m16n8k16.row.col.f32.f16.f16.f32 "
                 "{%0,%1,%2,%3}, {%4,%5,%6,%7}, {%8,%9}, {%0,%1,%2,%3};"
                 : "+f"(c[0]), "+f"(c[1]), "+f"(c[2]), "+f"(c[3])
                 : "r"(a[0]), "r"(a[1]), "r"(a[2]), "r"(a[3]), "r"(b[0]), "r"(b[1]));
}
__device__ __forceinline__ uint32_t packh2(float a, float b) {
    __half2 h = __floats2half2_rn(a, b);
    return *(uint32_t*)&h;
}

// ===========================================================================
// fp16 GEMM (NT): C[m,n] = sum_k A[m,k]*B[n,k] + bias[n]   (fp32 accumulate)
// Block tile 256x128, BK=64 halves, 3-stage cp.async, 256 thr.
// EPI==0: row-major store. EPI==1: qkv scatter (fp32 to out + fp16 copies).
// ===========================================================================
#define GF_ASTG 36864u
#define GF_BSTG 18432u
#define GF_SMEM 165888

template<int EPI>
__global__ void __launch_bounds__(256, 1)
gemm_fp16(const __half* __restrict__ A, const __half* __restrict__ B,
          const float* __restrict__ bias, float* __restrict__ C,
          int M, int N, int K,
          float* __restrict__ oQ, float* __restrict__ oK, float* __restrict__ oV,
          __half* __restrict__ oQh, __half* __restrict__ oKh, __half* __restrict__ oVh)
{
    extern __shared__ char smemc[];
    const uint32_t aBase = smem_u32(smemc);
    const uint32_t bBase = aBase + 3u * GF_ASTG;

    const int tid = threadIdx.x;
    const int lane = tid & 31, wid = tid >> 5;
    const int m0 = blockIdx.y << 8;
    const int n0 = blockIdx.x << 7;
    const int wm = (wid & 3) << 6;
    const int wn = (wid >> 2) << 6;

    const int grow = tid >> 3;
    const int gc8  = (tid & 7) << 3;
    const __half* Ag = A + (size_t)(m0 + grow) * K + gc8;
    const __half* Bg = B + (size_t)(n0 + grow) * K + gc8;
    const uint32_t sOff = (uint32_t)((grow * 72 + gc8) << 1);

    const int rA = lane & 15, cA = (lane >> 4) << 3;
    const int rB = (lane & 7) + ((lane >> 4) << 3);
    const int cB = ((lane >> 3) & 1) << 3;

#define GF_LOAD(stage, kb) do {                                                \
    const __half* _a = Ag + ((kb) << 6);                                       \
    const __half* _b = Bg + ((kb) << 6);                                       \
    const uint32_t _da = aBase + (uint32_t)(stage) * GF_ASTG + sOff;           \
    const uint32_t _db = bBase + (uint32_t)(stage) * GF_BSTG + sOff;           \
    _Pragma("unroll")                                                          \
    for (int _p = 0; _p < 8; _p++)                                             \
        cp16(_da + (uint32_t)_p * 4608u, _a + (size_t)(_p << 5) * K);          \
    _Pragma("unroll")                                                          \
    for (int _p = 0; _p < 4; _p++)                                             \
        cp16(_db + (uint32_t)_p * 4608u, _b + (size_t)(_p << 5) * K);          \
    asm volatile("cp.async.commit_group;" ::: "memory");                       \
} while (0)

    float c[4][8][4];
#pragma unroll
    for (int i = 0; i < 4; i++)
#pragma unroll
        for (int j = 0; j < 8; j++)
#pragma unroll
            for (int r = 0; r < 4; r++) c[i][j][r] = 0.f;

    const int NK = K >> 6;
    GF_LOAD(0, 0);
    GF_LOAD(1, 1);

    for (int kb = 0; kb < NK; ++kb) {
        if (kb < NK - 1)
            asm volatile("cp.async.wait_group 1;" ::: "memory");
        else
            asm volatile("cp.async.wait_group 0;" ::: "memory");
        __syncthreads();

        if (kb + 2 < NK) {
            int ns = kb + 2; ns = ns - (ns / 3) * 3;
            GF_LOAD(ns, kb + 2);
        }

        int st = kb - (kb / 3) * 3;
        const uint32_t aS = aBase + (uint32_t)st * GF_ASTG;
        const uint32_t bS = bBase + (uint32_t)st * GF_BSTG;

#pragma unroll
        for (int ks = 0; ks < 4; ++ks) {
            uint32_t a[4][4];
#pragma unroll
            for (int i = 0; i < 4; i++)
                ldsm4(a[i], aS + (uint32_t)(((wm + i * 16 + rA) * 72 + cA + ks * 16) << 1));
            uint32_t b[8][2];
#pragma unroll
            for (int j2 = 0; j2 < 4; j2++) {
                uint32_t r4[4];
                ldsm4(r4, bS + (uint32_t)(((wn + j2 * 16 + rB) * 72 + cB + ks * 16) << 1));
                b[2 * j2 + 0][0] = r4[0]; b[2 * j2 + 0][1] = r4[1];
                b[2 * j2 + 1][0] = r4[2]; b[2 * j2 + 1][1] = r4[3];
            }
#pragma unroll
            for (int i = 0; i < 4; i++)
#pragma unroll
                for (int j = 0; j < 8; j++)
                    mma16(c[i][j], a[i], b[j]);
        }
    }
#undef GF_LOAD

    const int gro = lane >> 2;
    const int gco = (lane & 3) << 1;
#pragma unroll
    for (int i = 0; i < 4; i++) {
        const int r0 = m0 + wm + i * 16 + gro;
#pragma unroll
        for (int j = 0; j < 8; j++) {
            const int col = n0 + wn + j * 8 + gco;
            const float b0 = bias[col], b1 = bias[col + 1];
            if (EPI == 0) {
                float2 v0 = make_float2(c[i][j][0] + b0, c[i][j][1] + b1);
                float2 v1 = make_float2(c[i][j][2] + b0, c[i][j][3] + b1);
                *(float2*)(C + (size_t)r0 * N + col) = v0;
                *(float2*)(C + (size_t)(r0 + 8) * N + col) = v1;
            } else {
                const int part = col >> 10;
                const int rem  = col & 1023;
                const int h = rem >> 6, d = rem & 63;
                float* dst = (part == 0) ? oQ : (part == 1) ? oK : oV;
                __half* dsth = (part == 0) ? oQh : (part == 1) ? oKh : oVh;
#pragma unroll
                for (int half = 0; half < 2; half++) {
                    const int row = r0 + half * 8;
                    const int bb = row >> 10, s = row & 1023;
                    float vx = c[i][j][2 * half] + b0;
                    float vy = c[i][j][2 * half + 1] + b1;
                    const size_t idx = (size_t)(((bb * NHEAD + h) << 10) + s) * HD + d;
                    *(float2*)(dst + idx) = make_float2(vx, vy);
                    *(__half2*)(dsth + idx) = __floats2half2_rn(vx, vy);
                }
            }
        }
    }
}

// ---------------------------------------------------------------------------
// 128x128 tf32 GEMM (proven) — GEMM3 (small grid)
// ---------------------------------------------------------------------------
__global__ void __launch_bounds__(256)
gemm_tf32(const float* __restrict__ A, const float* __restrict__ B,
          const float* __restrict__ bias, float* __restrict__ C,
          int M, int N, int K)
{
    __shared__ float sA[2][128][20];
    __shared__ float sB[2][128][20];

    const int tid = threadIdx.x;
    const int lane = tid & 31, wid = tid >> 5;
    const int m0 = blockIdx.y << 7, n0 = blockIdx.x << 7;
    const int wm = (wid & 1) << 6;
    const int wn = (wid >> 1) << 5;

    const int grow = tid >> 1;
    const int gseg = (tid & 1) << 1;
    const float* Ag = A + (size_t)(m0 + grow) * K + (gseg << 2);
    const float* Bg = B + (size_t)(n0 + grow) * K + (gseg << 2);
    const uint32_t sOffLd = (uint32_t)(grow * 80 + (gseg << 4));

    const int tIn = lane & 7, sel = lane >> 3;
    const int rAl = tIn + ((sel & 1) << 3);
    const int cAl = (sel & 2) << 1;
    const int rBl = tIn + ((sel & 2) << 2);
    const int cBl = (sel & 1) << 2;

    const uint32_t aBase = smem_u32(&sA[0][0][0]);
    const uint32_t bBase = smem_u32(&sB[0][0][0]);

#define G_LOAD(slot, kblk) do {                                                \
    const float* _a = Ag + ((kblk) << 4);                                      \
    const float* _b = Bg + ((kblk) << 4);                                      \
    uint32_t _da = aBase + (uint32_t)(slot) * 10240u + sOffLd;                 \
    uint32_t _db = bBase + (uint32_t)(slot) * 10240u + sOffLd;                 \
    cp16(_da, _a); cp16(_da + 16, _a + 4);                                     \
    cp16(_db, _b); cp16(_db + 16, _b + 4);                                     \
    asm volatile("cp.async.commit_group;" ::: "memory");                       \
} while (0)

    float c[4][4][4];
#pragma unroll
    for (int i = 0; i < 4; i++)
#pragma unroll
        for (int j = 0; j < 4; j++)
#pragma unroll
            for (int r = 0; r < 4; r++) c[i][j][r] = 0.f;

    const int kIters = K >> 4;
    G_LOAD(0, 0);
    G_LOAD(1, 1);

    for (int it = 0; it < kIters; ++it) {
        if (it + 2 < kIters)
            asm volatile("cp.async.wait_group 1;" ::: "memory");
        else
            asm volatile("cp.async.wait_group 0;" ::: "memory");
        __syncthreads();

        const int st = it & 1;
        const uint32_t aS = aBase + (uint32_t)st * 10240u;
        const uint32_t bS = bBase + (uint32_t)st * 10240u;

#pragma unroll
        for (int ks = 0; ks < 2; ++ks) {
            uint32_t a[4][4];
#pragma unroll
            for (int i = 0; i < 4; i++) {
                uint32_t ad = aS + (uint32_t)(((wm + i * 16 + rAl) * 20 + ks * 8 + cAl) << 2);
                ldsm4(a[i], ad);
            }
            uint32_t b[4][2];
#pragma unroll
            for (int j2 = 0; j2 < 2; j2++) {
                uint32_t r4[4];
                uint32_t bd = bS + (uint32_t)(((wn + j2 * 16 + rBl) * 20 + ks * 8 + cBl) << 2);
                ldsm4(r4, bd);
                b[2 * j2 + 0][0] = r4[0]; b[2 * j2 + 0][1] = r4[1];
                b[2 * j2 + 1][0] = r4[2]; b[2 * j2 + 1][1] = r4[3];
            }
#pragma unroll
            for (int i = 0; i < 4; i++)
#pragma unroll
                for (int j = 0; j < 4; j++)
                    mma8(c[i][j], a[i], b[j]);
        }
        __syncthreads();
        if (it + 2 < kIters) G_LOAD(st, it + 2);
    }
#undef G_LOAD

    const int gro = lane >> 2;
    const int gco = (lane & 3) << 1;
#pragma unroll
    for (int i = 0; i < 4; i++) {
        const int r0 = m0 + wm + i * 16 + gro;
#pragma unroll
        for (int j = 0; j < 4; j++) {
            const int col = n0 + wn + j * 8 + gco;
            const float b0 = bias[col], b1 = bias[col + 1];
            float2 v0 = make_float2(c[i][j][0] + b0, c[i][j][1] + b1);
            float2 v1 = make_float2(c[i][j][2] + b0, c[i][j][3] + b1);
            *(float2*)(C + (size_t)r0 * N + col) = v0;
            *(float2*)(C + (size_t)(r0 + 8) * N + col) = v1;
        }
    }
}

// ---------------------------------------------------------------------------
// conversion kernels
// ---------------------------------------------------------------------------
__global__ void cvt_fp16_kernel(const float4* __restrict__ in, __half2* __restrict__ out)
{
    int i = blockIdx.x * blockDim.x + threadIdx.x;
    float4 v = in[i];
    out[2 * i + 0] = __floats2half2_rn(v.x, v.y);
    out[2 * i + 1] = __floats2half2_rn(v.z, v.w);
}
__global__ void cvt_tf32_kernel(const float4* __restrict__ in, float4* __restrict__ out)
{
    int i = blockIdx.x * blockDim.x + threadIdx.x;
    float4 v = in[i];
    v.x = tf32r(v.x); v.y = tf32r(v.y); v.z = tf32r(v.z); v.w = tf32r(v.w);
    out[i] = v;
}

// ---------------------------------------------------------------------------
// Gather mem rows + LayerNorm -> fp16
// ---------------------------------------------------------------------------
__device__ __forceinline__ float blockReduceSum(float v, float* red)
{
    __syncthreads();
    int lane = threadIdx.x & 31, wid = threadIdx.x >> 5;
#pragma unroll
    for (int o = 16; o; o >>= 1) v += __shfl_xor_sync(0xffffffffu, v, o);
    if (lane == 0) red[wid] = v;
    __syncthreads();
    if (wid == 0) {
        v = (lane < 8) ? red[lane] : 0.f;
#pragma unroll
        for (int o = 4; o; o >>= 1) v += __shfl_xor_sync(0xffffffffu, v, o);
        if (lane == 0) red[0] = v;
    }
    __syncthreads();
    return red[0];
}

__global__ void mem_ln_kernel(const float* __restrict__ pq,
                              const float* __restrict__ pk,
                              const float* __restrict__ pv)
{
    __shared__ float red[32];
    int row = blockIdx.x;
    int j  = row % NMEM;
    int bs = row / NMEM;
    int s = bs & 1023, b = bs >> 10;
    int l = j & 3;
    const float* src = (j < 4) ? pq : (j < 8) ? pk : pv;
    size_t base = (size_t)(l * BATCH + b) * (NHEAD * S_LEN * HD) + (size_t)s * HD;

    int t = threadIdx.x;
    float vals[4];
    float sum = 0.f;
#pragma unroll
    for (int u = 0; u < 4; u++) {
        int c = t + (u << 8);
        int h = c >> 6, d = c & 63;
        float v = __ldg(src + base + (size_t)h * (S_LEN * HD) + d);
        vals[u] = v; sum += v;
    }
    sum = blockReduceSum(sum, red);
    float mean = sum * (1.f / 1024.f);
    float sq = 0.f;
#pragma unroll
    for (int u = 0; u < 4; u++) { float dv = vals[u] - mean; sq += dv * dv; }
    sq = blockReduceSum(sq, red);
    float inv = rsqrtf(sq * (1.f / 1024.f) + 1e-5f);

    __half* orow = g_memlnh + (size_t)row * 1024;
#pragma unroll
    for (int u = 0; u < 4; u++)
        orow[t + (u << 8)] = __float2half_rn((vals[u] - mean) * inv);
}

// ===========================================================================
// Flash attention (fp16 tensor core) + 12-slot memory attention merge.
// CTA: 64 queries x one (b,h). 4 warps x 16 q-rows. 64-key tiles, double
// buffered cp.async. Q@K^T: A=Q frags (ldsm), B=K rows (ldsm). P@V:
// A=P (from softmax regs), B=V via ldsm.trans.
// ===========================================================================
__global__ void __launch_bounds__(128)
attn_fa(const __half* __restrict__ qh, const __half* __restrict__ kh,
        const __half* __restrict__ vh, const float* __restrict__ rkv,
        float* __restrict__ merged)
{
    __shared__ __half sQ[64 * 72];
    __shared__ __half sK[2][64 * 72];
    __shared__ __half sV[2][64 * 72];

    const int tid = threadIdx.x;
    const int lane = tid & 31, w = tid >> 5;
    const int bh = blockIdx.x, b = bh >> 4, h = bh & 15;
    const int qt = gridDim.y - 1 - blockIdx.y;   // heavy tiles first
    const int q0 = qt << 6;
    const int wr = w << 4;

    const uint32_t sQb = smem_u32(sQ);
    const uint32_t sKb = smem_u32(sK);
    const uint32_t sVb = smem_u32(sV);

    const int lrow = tid >> 1;
    const int lcol = (tid & 1) << 5;             // halves
    const __half* qg = qh + ((size_t)bh << 16);
    const __half* kg = kh + ((size_t)bh << 16);
    const __half* vg = vh + ((size_t)bh << 16);

#define LOADKV(bf, kt_) do {                                                   \
    const __half* _ks = kg + (((kt_) * 64 + lrow) << 6) + lcol;                \
    const __half* _vs = vg + (((kt_) * 64 + lrow) << 6) + lcol;                \
    uint32_t _kd = sKb + (uint32_t)(bf) * 9216u + ((lrow * 72 + lcol) << 1);   \
    uint32_t _vd = sVb + (uint32_t)(bf) * 9216u + ((lrow * 72 + lcol) << 1);   \
    cp16(_kd, _ks); cp16(_kd + 16, _ks + 8);                                   \
    cp16(_kd + 32, _ks + 16); cp16(_kd + 48, _ks + 24);                        \
    cp16(_vd, _vs); cp16(_vd + 16, _vs + 8);                                   \
    cp16(_vd + 32, _vs + 16); cp16(_vd + 48, _vs + 24);                        \
    asm volatile("cp.async.commit_group;" ::: "memory");                       \
} while (0)

    // Q tile load + KV tile 0 (one group)
    {
        const __half* src = qg + ((q0 + lrow) << 6) + lcol;
        uint32_t dst = sQb + ((lrow * 72 + lcol) << 1);
        cp16(dst, src); cp16(dst + 16, src + 8);
        cp16(dst + 32, src + 16); cp16(dst + 48, src + 24);
    }
    LOADKV(0, 0);
    asm volatile("cp.async.wait_group 0;" ::: "memory");
    __syncthreads();

    // Q A-frags (persistent): qa[ki] covers q rows wr..wr+15, d cols ki*16..+15
    uint32_t qa[4][4];
    {
        const int qm = lane >> 3, qr = lane & 7;
        const int qrow = wr + ((qm & 1) << 3) + qr;
        const int qcb = (qm >> 1) << 3;
#pragma unroll
        for (int ki = 0; ki < 4; ki++)
            ldsm4(qa[ki], sQb + ((qrow * 72 + qcb + ki * 16) << 1));
    }

    // ldsm address components for K (scores) and V (trans)
    const int km = lane >> 3, kr = lane & 7;
    const int kro = ((km >> 1) & 1) << 3;        // K: +8 keys for m2,m3
    const int kco = (km & 1) << 3;               // K: +8 d for m1,m3
    const int vko = (km & 1) << 3;               // V: +8 keys for m1,m3
    const int vco = ((km >> 1) & 1) << 3;        // V: +8 d for m2,m3

    float o[8][4];
#pragma unroll
    for (int j = 0; j < 8; j++)
#pragma unroll
        for (int e = 0; e < 4; e++) o[j][e] = 0.f;
    float mrow[2] = { -1e30f, -1e30f };
    float lrow_[2] = { 0.f, 0.f };

    const int rlane = lane >> 2, clane = (lane & 3) << 1;

    for (int kt = 0; kt <= qt; ++kt) {
        if (kt < qt) {
            LOADKV((kt + 1) & 1, kt + 1);
            asm volatile("cp.async.wait_group 1;" ::: "memory");
        } else {
            asm volatile("cp.async.wait_group 0;" ::: "memory");
        }
        __syncthreads();

        const uint32_t kS = sKb + (uint32_t)(kt & 1) * 9216u;
        const uint32_t vS = sVb + (uint32_t)(kt & 1) * 9216u;

        float sc[8][4];
#pragma unroll
        for (int j = 0; j < 8; j++)
#pragma unroll
            for (int e = 0; e < 4; e++) sc[j][e] = 0.f;

#pragma unroll
        for (int ks = 0; ks < 4; ++ks) {
#pragma unroll
            for (int j2 = 0; j2 < 4; ++j2) {
                uint32_t kb[4];
                ldsm4(kb, kS + (((j2 * 16 + kro + kr) * 72 + ks * 16 + kco) << 1));
                mma16(sc[2 * j2], qa[ks], kb);
                mma16(sc[2 * j2 + 1], qa[ks], kb + 2);
            }
        }

        // scale + causal mask (diagonal tile only)
#pragma unroll
        for (int j = 0; j < 8; j++)
#pragma unroll
            for (int e = 0; e < 4; e++) sc[j][e] *= SCALE;
        if (kt == qt) {
            const int r0 = wr + rlane;
#pragma unroll
            for (int j = 0; j < 8; j++) {
                const int c0 = 8 * j + clane;
                if (c0 > r0)     sc[j][0] = -1e30f;
                if (c0 + 1 > r0) sc[j][1] = -1e30f;
                if (c0 > r0 + 8)     sc[j][2] = -1e30f;
                if (c0 + 1 > r0 + 8) sc[j][3] = -1e30f;
            }
        }

        // online softmax (two row-halves per thread)
        float t0 = -1e30f, t1 = -1e30f;
#pragma unroll
        for (int j = 0; j < 8; j++) {
            t0 = fmaxf(t0, fmaxf(sc[j][0], sc[j][1]));
            t1 = fmaxf(t1, fmaxf(sc[j][2], sc[j][3]));
        }
        t0 = fmaxf(t0, __shfl_xor_sync(0xffffffffu, t0, 1));
        t0 = fmaxf(t0, __shfl_xor_sync(0xffffffffu, t0, 2));
        t1 = fmaxf(t1, __shfl_xor_sync(0xffffffffu, t1, 1));
        t1 = fmaxf(t1, __shfl_xor_sync(0xffffffffu, t1, 2));
        const float mn0 = fmaxf(mrow[0], t0), mn1 = fmaxf(mrow[1], t1);
        const float cr0 = __expf(mrow[0] - mn0), cr1 = __expf(mrow[1] - mn1);
        float s0 = 0.f, s1 = 0.f;
#pragma unroll
        for (int j = 0; j < 8; j++) {
            sc[j][0] = __expf(sc[j][0] - mn0);
            sc[j][1] = __expf(sc[j][1] - mn0);
            sc[j][2] = __expf(sc[j][2] - mn1);
            sc[j][3] = __expf(sc[j][3] - mn1);
            s0 += sc[j][0] + sc[j][1];
            s1 += sc[j][2] + sc[j][3];
        }
        s0 += __shfl_xor_sync(0xffffffffu, s0, 1);
        s0 += __shfl_xor_sync(0xffffffffu, s0, 2);
        s1 += __shfl_xor_sync(0xffffffffu, s1, 1);
        s1 += __shfl_xor_sync(0xffffffffu, s1, 2);
        lrow_[0] = lrow_[0] * cr0 + s0;
        lrow_[1] = lrow_[1] * cr1 + s1;
        mrow[0] = mn0; mrow[1] = mn1;
#pragma unroll
        for (int j = 0; j < 8; j++) {
            o[j][0] *= cr0; o[j][1] *= cr0;
            o[j][2] *= cr1; o[j][3] *= cr1;
        }

        // P @ V
#pragma unroll
        for (int kc = 0; kc < 4; ++kc) {
            uint32_t pa[4];
            pa[0] = packh2(sc[2 * kc][0], sc[2 * kc][1]);
            pa[1] = packh2(sc[2 * kc][2], sc[2 * kc][3]);
            pa[2] = packh2(sc[2 * kc + 1][0], sc[2 * kc + 1][1]);
            pa[3] = packh2(sc[2 * kc + 1][2], sc[2 * kc + 1][3]);
#pragma unroll
            for (int j2 = 0; j2 < 4; ++j2) {
                uint32_t vb[4];
                ldsm4t(vb, vS + (((kc * 16 + vko + kr) * 72 + j2 * 16 + vco) << 1));
                mma16(o[2 * j2], pa, vb);
                mma16(o[2 * j2 + 1], pa, vb + 2);
            }
        }
        __syncthreads();
    }
#undef LOADKV

    // -------- memory part: 12 slots from g_rkv (fp32), frag-layout merge ----
#pragma unroll
    for (int hh = 0; hh < 2; hh++) {
        const int s_idx = q0 + wr + rlane + (hh << 3);
        const float* rbase = rkv + ((size_t)((b << 10) + s_idx) * 12) * 2048 + (h << 6);
        float2 qv[8];
#pragma unroll
        for (int ki = 0; ki < 4; ki++) {
            qv[2 * ki]     = __half22float2(*(__half2*)&qa[ki][hh]);
            qv[2 * ki + 1] = __half22float2(*(__half2*)&qa[ki][2 + hh]);
        }
        float sm[12];
#pragma unroll
        for (int slot = 0; slot < NMEM; slot++) {
            const float* rp = rbase + slot * 2048;
            float part = 0.f;
#pragma unroll
            for (int i = 0; i < 8; i++) {
                float2 rv2 = *(const float2*)(rp + 8 * i + clane);
                part += qv[i].x * rv2.x + qv[i].y * rv2.y;
            }
            part += __shfl_xor_sync(0xffffffffu, part, 1);
            part += __shfl_xor_sync(0xffffffffu, part, 2);
            sm[slot] = part * SCALE;
        }
        float mx = sm[0];
#pragma unroll
        for (int slot = 1; slot < NMEM; slot++) mx = fmaxf(mx, sm[slot]);
        const float mn = fmaxf(mrow[hh], mx);
        const float corr = __expf(mrow[hh] - mn);
        float p[12], psum = 0.f;
#pragma unroll
        for (int slot = 0; slot < NMEM; slot++) {
            p[slot] = __expf(sm[slot] - mn);
            psum += p[slot];
        }
        const float lf = lrow_[hh] * corr + psum;
#pragma unroll
        for (int j = 0; j < 8; j++) {
            o[j][2 * hh] *= corr; o[j][2 * hh + 1] *= corr;
        }
#pragma unroll
        for (int slot = 0; slot < NMEM; slot++) {
            const float* vp = rbase + slot * 2048 + 1024;
#pragma unroll
            for (int j = 0; j < 8; j++) {
                float2 v2 = *(const float2*)(vp + 8 * j + clane);
                o[j][2 * hh] += p[slot] * v2.x;
                o[j][2 * hh + 1] += p[slot] * v2.y;
            }
        }
        const float inv = 1.f / lf;
        float* op = merged + ((size_t)((b << 10) + s_idx) << 10) + (h << 6);
#pragma unroll
        for (int j = 0; j < 8; j++) {
            float2 st = make_float2(tf32r(o[j][2 * hh] * inv),
                                    tf32r(o[j][2 * hh + 1] * inv));
            *(float2*)(op + 8 * j + clane) = st;
        }
    }
}

// ---------------------------------------------------------------------------
// launch
// ---------------------------------------------------------------------------
extern "C" void kernel_launch(void* const* d_in, const int* in_sizes, int n_in,
                              void* d_out, int out_size)
{
    const float* x     = (const float*)d_in[0];
    const float* pastk = (const float*)d_in[1];
    const float* pastv = (const float*)d_in[2];
    const float* pastq = (const float*)d_in[3];
    const float* Wqkv  = (const float*)d_in[4];
    const float* bqkv  = (const float*)d_in[5];
    const float* Wout  = (const float*)d_in[6];
    const float* bout  = (const float*)d_in[7];

    float* out = (float*)d_out;                 // (B,S,D)
    float* oK  = out + (size_t)2097152;         // (B,H,S,hd)
    float* oV  = out + (size_t)2 * 2097152;
    float* oQ  = out + (size_t)3 * 2097152;

    static __half* s_memlnh = nullptr;
    static __half* s_xh = nullptr;
    static __half* s_wqkvh = nullptr;
    static __half* s_qh = nullptr;
    static __half* s_kh = nullptr;
    static __half* s_vh = nullptr;
    static float* s_rkv = nullptr;
    static float* s_merged = nullptr;
    static float* s_wout = nullptr;
    if (!s_memlnh) {
        cudaGetSymbolAddress((void**)&s_memlnh, g_memlnh);
        cudaGetSymbolAddress((void**)&s_xh, g_xh);
        cudaGetSymbolAddress((void**)&s_wqkvh, g_wqkvh);
        cudaGetSymbolAddress((void**)&s_qh, g_qhh);
        cudaGetSymbolAddress((void**)&s_kh, g_khh);
        cudaGetSymbolAddress((void**)&s_vh, g_vhh);
        cudaGetSymbolAddress((void**)&s_rkv, g_rkv);
        cudaGetSymbolAddress((void**)&s_merged, g_merged);
        cudaGetSymbolAddress((void**)&s_wout, g_wout);
        cudaFuncSetAttribute(gemm_fp16<0>, cudaFuncAttributeMaxDynamicSharedMemorySize,
                             GF_SMEM);
        cudaFuncSetAttribute(gemm_fp16<1>, cudaFuncAttributeMaxDynamicSharedMemorySize,
                             GF_SMEM);
    }

    // 0) convert operands
    cvt_fp16_kernel<<<2048, 256>>>((const float4*)x,    (__half2*)s_xh);
    cvt_fp16_kernel<<<3072, 256>>>((const float4*)Wqkv, (__half2*)s_wqkvh);
    cvt_tf32_kernel<<<1024, 256>>>((const float4*)Wout, (float4*)s_wout);

    // 1) qkv projection: fp32 scatter into out regions + fp16 copies
    {
        dim3 g(3072 / 128, 2048 / 256);
        gemm_fp16<1><<<g, 256, GF_SMEM>>>(s_xh, s_wqkvh, bqkv, nullptr,
                                          2048, 3072, 1024, oQ, oK, oV,
                                          s_qh, s_kh, s_vh);
    }
    // 2) mem gather + LayerNorm -> fp16
    mem_ln_kernel<<<24576, 256>>>(pastq, pastk, pastv);
    // 3) rk/rv projection (fp16 tensor core)
    {
        dim3 g(2048 / 128, 24576 / 256);
        gemm_fp16<0><<<g, 256, GF_SMEM>>>(s_memlnh, s_wqkvh + (size_t)1024 * 1024,
                                          bqkv + 1024, s_rkv, 24576, 2048, 1024,
                                          nullptr, nullptr, nullptr,
                                          nullptr, nullptr, nullptr);
    }
    // 4) flash attention (tensor core) + memory-slot merge
    {
        dim3 g(BATCH * NHEAD, 16);
        attn_fa<<<g, 128>>>(s_qh, s_kh, s_vh, s_rkv, s_merged);
    }
    // 5) output projection (tf32, 128x128)
    {
        dim3 g(1024 / 128, 2048 / 128);
        gemm_tf32<<<g, 256>>>(s_merged, s_wout, bout, out, 2048, 1024, 1024);
    }
}

// round 12
// speedup vs baseline: 10.3094x; 1.5165x over previous
#include <cuda_runtime.h>
#include <cuda_fp16.h>
#include <cstdint>

// Problem constants
#define BATCH   2
#define S_LEN   1024
#define D_DIM   1024
#define NHEAD   16
#define HD      64
#define NMEM    12          // 3*L
#define SCALE   0.125f      // 1/sqrt(64)

// ---------------------------------------------------------------------------
// Scratch (device globals: allocation-free)
// ---------------------------------------------------------------------------
__device__ __align__(16) __half g_memlnh[(size_t)24576 * 1024]; // LN'd mem rows (fp16)
__device__ __align__(16) __half g_xh    [(size_t)2048 * 1024];  // fp16 x
__device__ __align__(16) __half g_wqkvh [(size_t)3072 * 1024];  // fp16 Wqkv
__device__ __align__(16) __half g_qhh   [(size_t)2048 * 1024];  // fp16 q (B,H,S,hd)
__device__ __align__(16) __half g_khh   [(size_t)2048 * 1024];  // fp16 k
__device__ __align__(16) __half g_vhh   [(size_t)2048 * 1024];  // fp16 v
__device__ __align__(16) __half g_wkT   [(size_t)1024 * 1024];  // fp16 Wk^T
__device__ __align__(16) __half g_qp    [(size_t)2048 * 16 * 1024]; // Wk^T q per (bs,h)
__device__ __align__(16) __half g_ctx   [(size_t)2048 * 16 * 1024]; // sum_m w_m*memln
__device__ float g_ms  [(size_t)2048 * 16 * 12];  // mem scores
__device__ float g_pmn [(size_t)2048 * 16 * 12];  // normalized mem weights
__device__ float g_qb  [(size_t)2048 * 16];       // q . bk_h
__device__ float g_psum[(size_t)2048 * 16];       // sum_m pmn
__device__ float g_merged[(size_t)2048 * 1024];   // (B*S, D) attn out
__device__ float g_wout [(size_t)1024 * 1024];    // tf32-rounded Wout

// ---------------------------------------------------------------------------
// Helpers
// ---------------------------------------------------------------------------
__device__ __forceinline__ uint32_t smem_u32(const void* p) {
    uint32_t a;
    asm("{ .reg .u64 t; cvta.to.shared.u64 t, %1; cvt.u32.u64 %0, t; }" : "=r"(a) : "l"(p));
    return a;
}
__device__ __forceinline__ float tf32r(float x) {
    uint32_t u;
    asm("cvt.rna.tf32.f32 %0, %1;" : "=r"(u) : "f"(x));
    return __uint_as_float(u);
}
__device__ __forceinline__ void cp16(uint32_t dst, const void* src) {
    asm volatile("cp.async.cg.shared.global [%0], [%1], 16;" :: "r"(dst), "l"(src));
}
__device__ __forceinline__ void ldsm4(uint32_t* r, uint32_t addr) {
    asm volatile("ldmatrix.sync.aligned.m8n8.x4.shared.b16 {%0,%1,%2,%3}, [%4];"
                 : "=r"(r[0]), "=r"(r[1]), "=r"(r[2]), "=r"(r[3]) : "r"(addr));
}
__device__ __forceinline__ void ldsm4t(uint32_t* r, uint32_t addr) {
    asm volatile("ldmatrix.sync.aligned.m8n8.x4.trans.shared.b16 {%0,%1,%2,%3}, [%4];"
                 : "=r"(r[0]), "=r"(r[1]), "=r"(r[2]), "=r"(r[3]) : "r"(addr));
}
__device__ __forceinline__ void mma8(float* c, const uint32_t* a, const uint32_t* b) {
    asm volatile("mma.sync.aligned.m16n8k8.row.col.f32.tf32.tf32.f32 "
                 "{%0,%1,%2,%3}, {%4,%5,%6,%7}, {%8,%9}, {%0,%1,%2,%3};"
                 : "+f"(c[0]), "+f"(c[1]), "+f"(c[2]), "+f"(c[3])
                 : "r"(a[0]), "r"(a[1]), "r"(a[2]), "r"(a[3]), "r"(b[0]), "r"(b[1]));
}
__device__ __forceinline__ void mma16(float* c, const uint32_t* a, const uint32_t* b) {
    asm volatile("mma.sync.aligned.m16n8k16.row.col.f32.f16.f16.f32 "
                 "{%0,%1,%2,%3}, {%4,%5,%6,%7}, {%8,%9}, {%0,%1,%2,%3};"
                 : "+f"(c[0]), "+f"(c[1]), "+f"(c[2]), "+f"(c[3])
                 : "r"(a[0]), "r"(a[1]), "r"(a[2]), "r"(a[3]), "r"(b[0]), "r"(b[1]));
}
__device__ __forceinline__ uint32_t packh2(float a, float b) {
    __half2 h = __floats2half2_rn(a, b);
    return *(uint32_t*)&h;
}

// ===========================================================================
// fp16 GEMM (NT) — GEMM1 only: qkv projection with scatter epilogue
// ===========================================================================
#define GF_ASTG 36864u
#define GF_BSTG 18432u
#define GF_SMEM 165888

__global__ void __launch_bounds__(256, 1)
gemm_qkv(const __half* __restrict__ A, const __half* __restrict__ B,
         const float* __restrict__ bias,
         float* __restrict__ oQ, float* __restrict__ oK, float* __restrict__ oV,
         __half* __restrict__ oQh, __half* __restrict__ oKh, __half* __restrict__ oVh)
{
    extern __shared__ char smemc[];
    const uint32_t aBase = smem_u32(smemc);
    const uint32_t bBase = aBase + 3u * GF_ASTG;
    const int K = 1024;

    const int tid = threadIdx.x;
    const int lane = tid & 31, wid = tid >> 5;
    const int m0 = blockIdx.y << 8;
    const int n0 = blockIdx.x << 7;
    const int wm = (wid & 3) << 6;
    const int wn = (wid >> 2) << 6;

    const int grow = tid >> 3;
    const int gc8  = (tid & 7) << 3;
    const __half* Ag = A + (size_t)(m0 + grow) * K + gc8;
    const __half* Bg = B + (size_t)(n0 + grow) * K + gc8;
    const uint32_t sOff = (uint32_t)((grow * 72 + gc8) << 1);

    const int rA = lane & 15, cA = (lane >> 4) << 3;
    const int rB = (lane & 7) + ((lane >> 4) << 3);
    const int cB = ((lane >> 3) & 1) << 3;

#define GF_LOAD(stage, kb) do {                                                \
    const __half* _a = Ag + ((kb) << 6);                                       \
    const __half* _b = Bg + ((kb) << 6);                                       \
    const uint32_t _da = aBase + (uint32_t)(stage) * GF_ASTG + sOff;           \
    const uint32_t _db = bBase + (uint32_t)(stage) * GF_BSTG + sOff;           \
    _Pragma("unroll")                                                          \
    for (int _p = 0; _p < 8; _p++)                                             \
        cp16(_da + (uint32_t)_p * 4608u, _a + (size_t)(_p << 5) * K);          \
    _Pragma("unroll")                                                          \
    for (int _p = 0; _p < 4; _p++)                                             \
        cp16(_db + (uint32_t)_p * 4608u, _b + (size_t)(_p << 5) * K);          \
    asm volatile("cp.async.commit_group;" ::: "memory");                       \
} while (0)

    float c[4][8][4];
#pragma unroll
    for (int i = 0; i < 4; i++)
#pragma unroll
        for (int j = 0; j < 8; j++)
#pragma unroll
            for (int r = 0; r < 4; r++) c[i][j][r] = 0.f;

    const int NK = 16;
    GF_LOAD(0, 0);
    GF_LOAD(1, 1);

    for (int kb = 0; kb < NK; ++kb) {
        if (kb < NK - 1)
            asm volatile("cp.async.wait_group 1;" ::: "memory");
        else
            asm volatile("cp.async.wait_group 0;" ::: "memory");
        __syncthreads();

        if (kb + 2 < NK) {
            int ns = kb + 2; ns = ns - (ns / 3) * 3;
            GF_LOAD(ns, kb + 2);
        }

        int st = kb - (kb / 3) * 3;
        const uint32_t aS = aBase + (uint32_t)st * GF_ASTG;
        const uint32_t bS = bBase + (uint32_t)st * GF_BSTG;

#pragma unroll
        for (int ks = 0; ks < 4; ++ks) {
            uint32_t a[4][4];
#pragma unroll
            for (int i = 0; i < 4; i++)
                ldsm4(a[i], aS + (uint32_t)(((wm + i * 16 + rA) * 72 + cA + ks * 16) << 1));
            uint32_t b[8][2];
#pragma unroll
            for (int j2 = 0; j2 < 4; j2++) {
                uint32_t r4[4];
                ldsm4(r4, bS + (uint32_t)(((wn + j2 * 16 + rB) * 72 + cB + ks * 16) << 1));
                b[2 * j2 + 0][0] = r4[0]; b[2 * j2 + 0][1] = r4[1];
                b[2 * j2 + 1][0] = r4[2]; b[2 * j2 + 1][1] = r4[3];
            }
#pragma unroll
            for (int i = 0; i < 4; i++)
#pragma unroll
                for (int j = 0; j < 8; j++)
                    mma16(c[i][j], a[i], b[j]);
        }
    }
#undef GF_LOAD

    const int gro = lane >> 2;
    const int gco = (lane & 3) << 1;
#pragma unroll
    for (int i = 0; i < 4; i++) {
        const int r0 = m0 + wm + i * 16 + gro;
#pragma unroll
        for (int j = 0; j < 8; j++) {
            const int col = n0 + wn + j * 8 + gco;
            const float b0 = bias[col], b1 = bias[col + 1];
            const int part = col >> 10;
            const int rem  = col & 1023;
            const int h = rem >> 6, d = rem & 63;
            float* dst = (part == 0) ? oQ : (part == 1) ? oK : oV;
            __half* dsth = (part == 0) ? oQh : (part == 1) ? oKh : oVh;
#pragma unroll
            for (int half = 0; half < 2; half++) {
                const int row = r0 + half * 8;
                const int bb = row >> 10, s = row & 1023;
                float vx = c[i][j][2 * half] + b0;
                float vy = c[i][j][2 * half + 1] + b1;
                const size_t idx = (size_t)(((bb * NHEAD + h) << 10) + s) * HD + d;
                *(float2*)(dst + idx) = make_float2(vx, vy);
                *(__half2*)(dsth + idx) = __floats2half2_rn(vx, vy);
            }
        }
    }
}

// ---------------------------------------------------------------------------
// 128x128 tf32 GEMM (proven) — GEMM3
// ---------------------------------------------------------------------------
__global__ void __launch_bounds__(256)
gemm_tf32(const float* __restrict__ A, const float* __restrict__ B,
          const float* __restrict__ bias, float* __restrict__ C,
          int M, int N, int K)
{
    __shared__ float sA[2][128][20];
    __shared__ float sB[2][128][20];

    const int tid = threadIdx.x;
    const int lane = tid & 31, wid = tid >> 5;
    const int m0 = blockIdx.y << 7, n0 = blockIdx.x << 7;
    const int wm = (wid & 1) << 6;
    const int wn = (wid >> 1) << 5;

    const int grow = tid >> 1;
    const int gseg = (tid & 1) << 1;
    const float* Ag = A + (size_t)(m0 + grow) * K + (gseg << 2);
    const float* Bg = B + (size_t)(n0 + grow) * K + (gseg << 2);
    const uint32_t sOffLd = (uint32_t)(grow * 80 + (gseg << 4));

    const int tIn = lane & 7, sel = lane >> 3;
    const int rAl = tIn + ((sel & 1) << 3);
    const int cAl = (sel & 2) << 1;
    const int rBl = tIn + ((sel & 2) << 2);
    const int cBl = (sel & 1) << 2;

    const uint32_t aBase = smem_u32(&sA[0][0][0]);
    const uint32_t bBase = smem_u32(&sB[0][0][0]);

#define G_LOAD(slot, kblk) do {                                                \
    const float* _a = Ag + ((kblk) << 4);                                      \
    const float* _b = Bg + ((kblk) << 4);                                      \
    uint32_t _da = aBase + (uint32_t)(slot) * 10240u + sOffLd;                 \
    uint32_t _db = bBase + (uint32_t)(slot) * 10240u + sOffLd;                 \
    cp16(_da, _a); cp16(_da + 16, _a + 4);                                     \
    cp16(_db, _b); cp16(_db + 16, _b + 4);                                     \
    asm volatile("cp.async.commit_group;" ::: "memory");                       \
} while (0)

    float c[4][4][4];
#pragma unroll
    for (int i = 0; i < 4; i++)
#pragma unroll
        for (int j = 0; j < 4; j++)
#pragma unroll
            for (int r = 0; r < 4; r++) c[i][j][r] = 0.f;

    const int kIters = K >> 4;
    G_LOAD(0, 0);
    G_LOAD(1, 1);

    for (int it = 0; it < kIters; ++it) {
        if (it + 2 < kIters)
            asm volatile("cp.async.wait_group 1;" ::: "memory");
        else
            asm volatile("cp.async.wait_group 0;" ::: "memory");
        __syncthreads();

        const int st = it & 1;
        const uint32_t aS = aBase + (uint32_t)st * 10240u;
        const uint32_t bS = bBase + (uint32_t)st * 10240u;

#pragma unroll
        for (int ks = 0; ks < 2; ++ks) {
            uint32_t a[4][4];
#pragma unroll
            for (int i = 0; i < 4; i++) {
                uint32_t ad = aS + (uint32_t)(((wm + i * 16 + rAl) * 20 + ks * 8 + cAl) << 2);
                ldsm4(a[i], ad);
            }
            uint32_t b[4][2];
#pragma unroll
            for (int j2 = 0; j2 < 2; j2++) {
                uint32_t r4[4];
                uint32_t bd = bS + (uint32_t)(((wn + j2 * 16 + rBl) * 20 + ks * 8 + cBl) << 2);
                ldsm4(r4, bd);
                b[2 * j2 + 0][0] = r4[0]; b[2 * j2 + 0][1] = r4[1];
                b[2 * j2 + 1][0] = r4[2]; b[2 * j2 + 1][1] = r4[3];
            }
#pragma unroll
            for (int i = 0; i < 4; i++)
#pragma unroll
                for (int j = 0; j < 4; j++)
                    mma8(c[i][j], a[i], b[j]);
        }
        __syncthreads();
        if (it + 2 < kIters) G_LOAD(st, it + 2);
    }
#undef G_LOAD

    const int gro = lane >> 2;
    const int gco = (lane & 3) << 1;
#pragma unroll
    for (int i = 0; i < 4; i++) {
        const int r0 = m0 + wm + i * 16 + gro;
#pragma unroll
        for (int j = 0; j < 4; j++) {
            const int col = n0 + wn + j * 8 + gco;
            const float b0 = bias[col], b1 = bias[col + 1];
            float2 v0 = make_float2(c[i][j][0] + b0, c[i][j][1] + b1);
            float2 v1 = make_float2(c[i][j][2] + b0, c[i][j][3] + b1);
            *(float2*)(C + (size_t)r0 * N + col) = v0;
            *(float2*)(C + (size_t)(r0 + 8) * N + col) = v1;
        }
    }
}

// ---------------------------------------------------------------------------
// conversion / transpose kernels
// ---------------------------------------------------------------------------
__global__ void cvt_fp16_kernel(const float4* __restrict__ in, __half2* __restrict__ out)
{
    int i = blockIdx.x * blockDim.x + threadIdx.x;
    float4 v = in[i];
    out[2 * i + 0] = __floats2half2_rn(v.x, v.y);
    out[2 * i + 1] = __floats2half2_rn(v.z, v.w);
}
__global__ void cvt_tf32_kernel(const float4* __restrict__ in, float4* __restrict__ out)
{
    int i = blockIdx.x * blockDim.x + threadIdx.x;
    float4 v = in[i];
    v.x = tf32r(v.x); v.y = tf32r(v.y); v.z = tf32r(v.z); v.w = tf32r(v.w);
    out[i] = v;
}
// Wk^T: o[n][j] = Wk[j][n]  (Wk = Wqkv rows 1024..2047), fp16 output
__global__ void k_wkT(const float* __restrict__ wk, __half* __restrict__ o)
{
    __shared__ float t[32][33];
    int x = (blockIdx.x << 5) + threadIdx.x;   // input col n
    int y = (blockIdx.y << 5) + threadIdx.y;   // input row j
#pragma unroll
    for (int i = 0; i < 32; i += 8)
        t[threadIdx.y + i][threadIdx.x] = wk[(size_t)(y + i) * 1024 + x];
    __syncthreads();
    x = (blockIdx.y << 5) + threadIdx.x;       // out col j
    y = (blockIdx.x << 5) + threadIdx.y;       // out row n
#pragma unroll
    for (int i = 0; i < 32; i += 8)
        o[(size_t)(y + i) * 1024 + x] = __float2half_rn(t[threadIdx.x][threadIdx.y + i]);
}

// ---------------------------------------------------------------------------
// Gather mem rows + LayerNorm -> fp16
// ---------------------------------------------------------------------------
__device__ __forceinline__ float blockReduceSum(float v, float* red)
{
    __syncthreads();
    int lane = threadIdx.x & 31, wid = threadIdx.x >> 5;
#pragma unroll
    for (int o = 16; o; o >>= 1) v += __shfl_xor_sync(0xffffffffu, v, o);
    if (lane == 0) red[wid] = v;
    __syncthreads();
    if (wid == 0) {
        v = (lane < 8) ? red[lane] : 0.f;
#pragma unroll
        for (int o = 4; o; o >>= 1) v += __shfl_xor_sync(0xffffffffu, v, o);
        if (lane == 0) red[0] = v;
    }
    __syncthreads();
    return red[0];
}

__global__ void mem_ln_kernel(const float* __restrict__ pq,
                              const float* __restrict__ pk,
                              const float* __restrict__ pv)
{
    __shared__ float red[32];
    int row = blockIdx.x;
    int j  = row % NMEM;
    int bs = row / NMEM;
    int s = bs & 1023, b = bs >> 10;
    int l = j & 3;
    const float* src = (j < 4) ? pq : (j < 8) ? pk : pv;
    size_t base = (size_t)(l * BATCH + b) * (NHEAD * S_LEN * HD) + (size_t)s * HD;

    int t = threadIdx.x;
    float vals[4];
    float sum = 0.f;
#pragma unroll
    for (int u = 0; u < 4; u++) {
        int c = t + (u << 8);
        int h = c >> 6, d = c & 63;
        float v = __ldg(src + base + (size_t)h * (S_LEN * HD) + d);
        vals[u] = v; sum += v;
    }
    sum = blockReduceSum(sum, red);
    float mean = sum * (1.f / 1024.f);
    float sq = 0.f;
#pragma unroll
    for (int u = 0; u < 4; u++) { float dv = vals[u] - mean; sq += dv * dv; }
    sq = blockReduceSum(sq, red);
    float inv = rsqrtf(sq * (1.f / 1024.f) + 1e-5f);

    __half* orow = g_memlnh + (size_t)row * 1024;
#pragma unroll
    for (int u = 0; u < 4; u++)
        orow[t + (u << 8)] = __float2half_rn((vals[u] - mean) * inv);
}

// ===========================================================================
// k_qp: qp[(bs,h),n] = sum_d q[b,h,s,d] * WkT[n, h*64+d]   (per-head proj)
// grid (8 n-tiles, 8 m-tiles, 32 z=(b,h)), 256 thr, tile 128x128, K=64.
// ===========================================================================
__global__ void __launch_bounds__(256)
k_qp(const __half* __restrict__ q, const __half* __restrict__ wkT,
     __half* __restrict__ qp)
{
    __shared__ __half sA[128 * 72];
    __shared__ __half sB[128 * 72];
    const int tid = threadIdx.x, lane = tid & 31, wid = tid >> 5;
    const int z = blockIdx.z, b = z >> 4, h = z & 15;
    const int m0 = blockIdx.y << 7, n0 = blockIdx.x << 7;
    const uint32_t aB = smem_u32(sA), bB = smem_u32(sB);

    {
        const int grow = tid >> 1, gc = (tid & 1) << 5;
        const __half* aSrc = q + ((size_t)z << 16) + ((size_t)(m0 + grow) << 6) + gc;
        const __half* bSrc = wkT + (size_t)(n0 + grow) * 1024 + (h << 6) + gc;
        uint32_t da = aB + (uint32_t)((grow * 72 + gc) << 1);
        uint32_t db = bB + (uint32_t)((grow * 72 + gc) << 1);
        cp16(da, aSrc); cp16(da + 16, aSrc + 8);
        cp16(da + 32, aSrc + 16); cp16(da + 48, aSrc + 24);
        cp16(db, bSrc); cp16(db + 16, bSrc + 8);
        cp16(db + 32, bSrc + 16); cp16(db + 48, bSrc + 24);
        asm volatile("cp.async.commit_group;\ncp.async.wait_group 0;" ::: "memory");
    }
    __syncthreads();

    const int wm = (wid & 1) << 6, wn = (wid >> 1) << 5;
    const int rA = lane & 15, cA = (lane >> 4) << 3;
    const int rB = (lane & 7) + ((lane >> 4) << 3);
    const int cB = ((lane >> 3) & 1) << 3;

    float c[4][4][4];
#pragma unroll
    for (int i = 0; i < 4; i++)
#pragma unroll
        for (int j = 0; j < 4; j++)
#pragma unroll
            for (int r = 0; r < 4; r++) c[i][j][r] = 0.f;

#pragma unroll
    for (int ks = 0; ks < 4; ++ks) {
        uint32_t a[4][4];
#pragma unroll
        for (int i = 0; i < 4; i++)
            ldsm4(a[i], aB + (uint32_t)(((wm + i * 16 + rA) * 72 + cA + ks * 16) << 1));
        uint32_t bb[4][2];
#pragma unroll
        for (int j2 = 0; j2 < 2; j2++) {
            uint32_t r4[4];
            ldsm4(r4, bB + (uint32_t)(((wn + j2 * 16 + rB) * 72 + cB + ks * 16) << 1));
            bb[2 * j2 + 0][0] = r4[0]; bb[2 * j2 + 0][1] = r4[1];
            bb[2 * j2 + 1][0] = r4[2]; bb[2 * j2 + 1][1] = r4[3];
        }
#pragma unroll
        for (int i = 0; i < 4; i++)
#pragma unroll
            for (int j = 0; j < 4; j++)
                mma16(c[i][j], a[i], bb[j]);
    }

    const int gro = lane >> 2, gco = (lane & 3) << 1;
#pragma unroll
    for (int i = 0; i < 4; i++) {
        const int row = m0 + wm + i * 16 + gro;
        __half* d0 = qp + ((size_t)((b << 10) + row) * 16 + h) * 1024;
        __half* d1 = d0 + (size_t)8 * 16 * 1024;   // row+8
#pragma unroll
        for (int j = 0; j < 4; j++) {
            const int col = n0 + wn + j * 8 + gco;
            *(__half2*)(d0 + col) = __floats2half2_rn(c[i][j][0], c[i][j][1]);
            *(__half2*)(d1 + col) = __floats2half2_rn(c[i][j][2], c[i][j][3]);
        }
    }
}

// ===========================================================================
// k_qb: qb[(bs,h)] = q[b,h,s,:] . bqkv[1024 + h*64 ..]
// ===========================================================================
__global__ void k_qb(const __half* __restrict__ q, const float* __restrict__ bqkv,
                     float* __restrict__ qb)
{
    __shared__ float sbk[64];
    const int z = blockIdx.x, b = z >> 4, h = z & 15;
    if (threadIdx.x < 64) sbk[threadIdx.x] = bqkv[1024 + (h << 6) + threadIdx.x];
    __syncthreads();
    for (int s = threadIdx.x; s < 1024; s += 256) {
        const __half2* qr = (const __half2*)(q + ((size_t)z << 16) + ((size_t)s << 6));
        float acc = 0.f;
#pragma unroll
        for (int i = 0; i < 32; i++) {
            float2 f = __half22float2(qr[i]);
            acc += f.x * sbk[2 * i] + f.y * sbk[2 * i + 1];
        }
        qb[(size_t)((b << 10) + s) * 16 + h] = acc;
    }
}

// ===========================================================================
// k_ms: mem scores[(bs,h),m] = (qp[bs,h,:].memln[bs,m,:] + qb)*SCALE
// CTA per bs, 512 thr = 16 warps (one per h), memln shared in smem.
// ===========================================================================
__global__ void __launch_bounds__(512)
k_ms(const __half* __restrict__ qp, const __half* __restrict__ memln,
     const float* __restrict__ qb, float* __restrict__ ms)
{
    __shared__ __align__(16) __half sm[12 * 1024];
    const int bs = blockIdx.x;
    const int tid = threadIdx.x, lane = tid & 31, w = tid >> 5;
    const __half* mlb = memln + (size_t)bs * 12288;
    for (int u = tid; u < 1536; u += 512)
        ((float4*)sm)[u] = ((const float4*)mlb)[u];

    const __half* qpr = qp + ((size_t)bs * 16 + w) * 1024;
    float4 qf[4];
#pragma unroll
    for (int i = 0; i < 4; i++) qf[i] = ((const float4*)qpr)[i * 32 + lane];
    __syncthreads();

    const float qbv = qb[(size_t)bs * 16 + w];
#pragma unroll
    for (int m = 0; m < NMEM; m++) {
        float acc = 0.f;
#pragma unroll
        for (int i = 0; i < 4; i++) {
            float4 mf = ((const float4*)sm)[m * 128 + i * 32 + lane];
            const __half2* qh2 = (const __half2*)&qf[i];
            const __half2* mh2 = (const __half2*)&mf;
#pragma unroll
            for (int jj = 0; jj < 4; jj++) {
                float2 a = __half22float2(qh2[jj]);
                float2 c2 = __half22float2(mh2[jj]);
                acc += a.x * c2.x + a.y * c2.y;
            }
        }
#pragma unroll
        for (int o = 16; o; o >>= 1) acc += __shfl_xor_sync(0xffffffffu, acc, o);
        if (lane == 0) ms[((size_t)bs * 16 + w) * 12 + m] = (acc + qbv) * SCALE;
    }
}

// ===========================================================================
// Flash attention (fp16 tc) token part + merge with precomputed mem scores.
// Outputs: merged (token context, unnormalized-by-mem... fully normalized),
//          pmn = exp(ms - m_f)/l_f
// ===========================================================================
__global__ void __launch_bounds__(128)
attn_fa(const __half* __restrict__ qh, const __half* __restrict__ kh,
        const __half* __restrict__ vh, const float* __restrict__ ms,
        float* __restrict__ pmn, float* __restrict__ merged)
{
    __shared__ __half sQ[64 * 72];
    __shared__ __half sK[2][64 * 72];
    __shared__ __half sV[2][64 * 72];

    const int tid = threadIdx.x;
    const int lane = tid & 31, w = tid >> 5;
    const int bh = blockIdx.x, b = bh >> 4, h = bh & 15;
    const int qt = gridDim.y - 1 - blockIdx.y;
    const int q0 = qt << 6;
    const int wr = w << 4;

    const uint32_t sQb = smem_u32(sQ);
    const uint32_t sKb = smem_u32(sK);
    const uint32_t sVb = smem_u32(sV);

    const int lrow = tid >> 1;
    const int lcol = (tid & 1) << 5;
    const __half* qg = qh + ((size_t)bh << 16);
    const __half* kg = kh + ((size_t)bh << 16);
    const __half* vg = vh + ((size_t)bh << 16);

#define LOADKV(bf, kt_) do {                                                   \
    const __half* _ks = kg + (((kt_) * 64 + lrow) << 6) + lcol;                \
    const __half* _vs = vg + (((kt_) * 64 + lrow) << 6) + lcol;                \
    uint32_t _kd = sKb + (uint32_t)(bf) * 9216u + ((lrow * 72 + lcol) << 1);   \
    uint32_t _vd = sVb + (uint32_t)(bf) * 9216u + ((lrow * 72 + lcol) << 1);   \
    cp16(_kd, _ks); cp16(_kd + 16, _ks + 8);                                   \
    cp16(_kd + 32, _ks + 16); cp16(_kd + 48, _ks + 24);                        \
    cp16(_vd, _vs); cp16(_vd + 16, _vs + 8);                                   \
    cp16(_vd + 32, _vs + 16); cp16(_vd + 48, _vs + 24);                        \
    asm volatile("cp.async.commit_group;" ::: "memory");                       \
} while (0)

    {
        const __half* src = qg + ((q0 + lrow) << 6) + lcol;
        uint32_t dst = sQb + ((lrow * 72 + lcol) << 1);
        cp16(dst, src); cp16(dst + 16, src + 8);
        cp16(dst + 32, src + 16); cp16(dst + 48, src + 24);
    }
    LOADKV(0, 0);
    asm volatile("cp.async.wait_group 0;" ::: "memory");
    __syncthreads();

    uint32_t qa[4][4];
    {
        const int qm = lane >> 3, qr = lane & 7;
        const int qrow = wr + ((qm & 1) << 3) + qr;
        const int qcb = (qm >> 1) << 3;
#pragma unroll
        for (int ki = 0; ki < 4; ki++)
            ldsm4(qa[ki], sQb + ((qrow * 72 + qcb + ki * 16) << 1));
    }

    const int km = lane >> 3, kr = lane & 7;
    const int kro = ((km >> 1) & 1) << 3;
    const int kco = (km & 1) << 3;
    const int vko = (km & 1) << 3;
    const int vco = ((km >> 1) & 1) << 3;

    float o[8][4];
#pragma unroll
    for (int j = 0; j < 8; j++)
#pragma unroll
        for (int e = 0; e < 4; e++) o[j][e] = 0.f;
    float mrow[2] = { -1e30f, -1e30f };
    float lrow_[2] = { 0.f, 0.f };

    const int rlane = lane >> 2, clane = (lane & 3) << 1;

    for (int kt = 0; kt <= qt; ++kt) {
        if (kt < qt) {
            LOADKV((kt + 1) & 1, kt + 1);
            asm volatile("cp.async.wait_group 1;" ::: "memory");
        } else {
            asm volatile("cp.async.wait_group 0;" ::: "memory");
        }
        __syncthreads();

        const uint32_t kS = sKb + (uint32_t)(kt & 1) * 9216u;
        const uint32_t vS = sVb + (uint32_t)(kt & 1) * 9216u;

        float sc[8][4];
#pragma unroll
        for (int j = 0; j < 8; j++)
#pragma unroll
            for (int e = 0; e < 4; e++) sc[j][e] = 0.f;

#pragma unroll
        for (int ks = 0; ks < 4; ++ks) {
#pragma unroll
            for (int j2 = 0; j2 < 4; ++j2) {
                uint32_t kb[4];
                ldsm4(kb, kS + (((j2 * 16 + kro + kr) * 72 + ks * 16 + kco) << 1));
                mma16(sc[2 * j2], qa[ks], kb);
                mma16(sc[2 * j2 + 1], qa[ks], kb + 2);
            }
        }

#pragma unroll
        for (int j = 0; j < 8; j++)
#pragma unroll
            for (int e = 0; e < 4; e++) sc[j][e] *= SCALE;
        if (kt == qt) {
            const int r0 = wr + rlane;
#pragma unroll
            for (int j = 0; j < 8; j++) {
                const int c0 = 8 * j + clane;
                if (c0 > r0)     sc[j][0] = -1e30f;
                if (c0 + 1 > r0) sc[j][1] = -1e30f;
                if (c0 > r0 + 8)     sc[j][2] = -1e30f;
                if (c0 + 1 > r0 + 8) sc[j][3] = -1e30f;
            }
        }

        float t0 = -1e30f, t1 = -1e30f;
#pragma unroll
        for (int j = 0; j < 8; j++) {
            t0 = fmaxf(t0, fmaxf(sc[j][0], sc[j][1]));
            t1 = fmaxf(t1, fmaxf(sc[j][2], sc[j][3]));
        }
        t0 = fmaxf(t0, __shfl_xor_sync(0xffffffffu, t0, 1));
        t0 = fmaxf(t0, __shfl_xor_sync(0xffffffffu, t0, 2));
        t1 = fmaxf(t1, __shfl_xor_sync(0xffffffffu, t1, 1));
        t1 = fmaxf(t1, __shfl_xor_sync(0xffffffffu, t1, 2));
        const float mn0 = fmaxf(mrow[0], t0), mn1 = fmaxf(mrow[1], t1);
        const float cr0 = __expf(mrow[0] - mn0), cr1 = __expf(mrow[1] - mn1);
        float s0 = 0.f, s1 = 0.f;
#pragma unroll
        for (int j = 0; j < 8; j++) {
            sc[j][0] = __expf(sc[j][0] - mn0);
            sc[j][1] = __expf(sc[j][1] - mn0);
            sc[j][2] = __expf(sc[j][2] - mn1);
            sc[j][3] = __expf(sc[j][3] - mn1);
            s0 += sc[j][0] + sc[j][1];
            s1 += sc[j][2] + sc[j][3];
        }
        s0 += __shfl_xor_sync(0xffffffffu, s0, 1);
        s0 += __shfl_xor_sync(0xffffffffu, s0, 2);
        s1 += __shfl_xor_sync(0xffffffffu, s1, 1);
        s1 += __shfl_xor_sync(0xffffffffu, s1, 2);
        lrow_[0] = lrow_[0] * cr0 + s0;
        lrow_[1] = lrow_[1] * cr1 + s1;
        mrow[0] = mn0; mrow[1] = mn1;
#pragma unroll
        for (int j = 0; j < 8; j++) {
            o[j][0] *= cr0; o[j][1] *= cr0;
            o[j][2] *= cr1; o[j][3] *= cr1;
        }

#pragma unroll
        for (int kc = 0; kc < 4; ++kc) {
            uint32_t pa[4];
            pa[0] = packh2(sc[2 * kc][0], sc[2 * kc][1]);
            pa[1] = packh2(sc[2 * kc][2], sc[2 * kc][3]);
            pa[2] = packh2(sc[2 * kc + 1][0], sc[2 * kc + 1][1]);
            pa[3] = packh2(sc[2 * kc + 1][2], sc[2 * kc + 1][3]);
#pragma unroll
            for (int j2 = 0; j2 < 4; ++j2) {
                uint32_t vb[4];
                ldsm4t(vb, vS + (((kc * 16 + vko + kr) * 72 + j2 * 16 + vco) << 1));
                mma16(o[2 * j2], pa, vb);
                mma16(o[2 * j2 + 1], pa, vb + 2);
            }
        }
        __syncthreads();
    }
#undef LOADKV

    // merge precomputed memory scores; write token part + normalized weights
#pragma unroll
    for (int hh = 0; hh < 2; hh++) {
        const int s_idx = q0 + wr + rlane + (hh << 3);
        const size_t bsh = (size_t)((b << 10) + s_idx) * 16 + h;
        const float* msp = ms + bsh * 12;
        float smv[12];
#pragma unroll
        for (int m = 0; m < NMEM; m++) smv[m] = msp[m];
        float mx = smv[0];
#pragma unroll
        for (int m = 1; m < NMEM; m++) mx = fmaxf(mx, smv[m]);
        const float mn = fmaxf(mrow[hh], mx);
        const float corr = __expf(mrow[hh] - mn);
        float p[12], ps = 0.f;
#pragma unroll
        for (int m = 0; m < NMEM; m++) { p[m] = __expf(smv[m] - mn); ps += p[m]; }
        const float lf = lrow_[hh] * corr + ps;
        const float inv = 1.f / lf;
        const float cf = corr * inv;
        if ((lane & 3) == 0) {
            float* pw = pmn + bsh * 12;
#pragma unroll
            for (int m = 0; m < NMEM; m++) pw[m] = p[m] * inv;
        }
        float* op = merged + ((size_t)((b << 10) + s_idx) << 10) + (h << 6);
#pragma unroll
        for (int j = 0; j < 8; j++)
            *(float2*)(op + 8 * j + clane) =
                make_float2(o[j][2 * hh] * cf, o[j][2 * hh + 1] * cf);
    }
}

// ===========================================================================
// k_ctx: ctx[(bs,h),k] = sum_m pmn[(bs,h),m]*memln[bs,m,k]; psum[(bs,h)]
// ===========================================================================
__global__ void __launch_bounds__(256)
k_ctx(const float* __restrict__ pmn, const __half* __restrict__ memln,
      __half* __restrict__ ctx, float* __restrict__ psum)
{
    __shared__ __align__(16) __half sm[12 * 1024];
    __shared__ float sp[192];
    const int bs = blockIdx.x, tid = threadIdx.x;
    const __half* mlb = memln + (size_t)bs * 12288;
    for (int u = tid; u < 1536; u += 256)
        ((float4*)sm)[u] = ((const float4*)mlb)[u];
    if (tid < 192) sp[tid] = pmn[(size_t)bs * 192 + tid];
    __syncthreads();
    if (tid < 16) {
        float s = 0.f;
#pragma unroll
        for (int m = 0; m < NMEM; m++) s += sp[tid * 12 + m];
        psum[(size_t)bs * 16 + tid] = s;
    }
    float mv[12][4];
#pragma unroll
    for (int m = 0; m < NMEM; m++) {
        float2 fx = __half22float2(*(__half2*)&sm[m * 1024 + (tid << 2)]);
        float2 fy = __half22float2(*(__half2*)&sm[m * 1024 + (tid << 2) + 2]);
        mv[m][0] = fx.x; mv[m][1] = fx.y; mv[m][2] = fy.x; mv[m][3] = fy.y;
    }
#pragma unroll
    for (int h = 0; h < 16; h++) {
        float o0 = 0.f, o1 = 0.f, o2 = 0.f, o3 = 0.f;
#pragma unroll
        for (int m = 0; m < NMEM; m++) {
            const float p = sp[h * 12 + m];
            o0 += p * mv[m][0]; o1 += p * mv[m][1];
            o2 += p * mv[m][2]; o3 += p * mv[m][3];
        }
        __half2* dst = (__half2*)(ctx + ((size_t)bs * 16 + h) * 1024 + (tid << 2));
        dst[0] = __floats2half2_rn(o0, o1);
        dst[1] = __floats2half2_rn(o2, o3);
    }
}

// ===========================================================================
// k_wv: merged[bs, h*64+d] += sum_k Wv[h*64+d,k]*ctx[(bs,h),k] + psum*bv
// grid (16 m-tiles, 16 h), 256 thr, tile 128x64, BK=64, 2-stage. Final tf32r.
// ===========================================================================
#define WV_ASTG 18432u
#define WV_BSTG 9216u
#define WV_SMEM (2 * (WV_ASTG + WV_BSTG))

__global__ void __launch_bounds__(256)
k_wv(const __half* __restrict__ ctx, const __half* __restrict__ wqkvh,
     const float* __restrict__ psum, const float* __restrict__ bqkv,
     float* __restrict__ merged)
{
    extern __shared__ char smemc[];
    const uint32_t aB = smem_u32(smemc);
    const uint32_t bB = aB + 2u * WV_ASTG;
    __shared__ float sbv[64];

    const int tid = threadIdx.x, lane = tid & 31, wid = tid >> 5;
    const int m0 = blockIdx.x << 7, h = blockIdx.y;
    if (tid < 64) sbv[tid] = bqkv[2048 + (h << 6) + tid];

    const __half* A = ctx + (size_t)h * 1024;             // row stride 16384
    const __half* B = wqkvh + (size_t)(2048 + (h << 6)) * 1024;

    const int agrow = tid >> 1, agc = (tid & 1) << 5;
    const int bgrow = tid >> 2, bgc = (tid & 3) << 4;

#define WV_LOAD(st, kb) do {                                                   \
    const __half* _a = A + (size_t)(m0 + agrow) * 16384 + ((kb) << 6) + agc;   \
    const __half* _b = B + (size_t)bgrow * 1024 + ((kb) << 6) + bgc;           \
    uint32_t _da = aB + (uint32_t)(st) * WV_ASTG + ((agrow * 72 + agc) << 1);  \
    uint32_t _db = bB + (uint32_t)(st) * WV_BSTG + ((bgrow * 72 + bgc) << 1);  \
    cp16(_da, _a); cp16(_da + 16, _a + 8);                                     \
    cp16(_da + 32, _a + 16); cp16(_da + 48, _a + 24);                          \
    cp16(_db, _b); cp16(_db + 16, _b + 8);                                     \
    asm volatile("cp.async.commit_group;" ::: "memory");                       \
} while (0)

    const int wm = (wid & 3) << 5, wn = (wid >> 2) << 5;
    const int rA = lane & 15, cA = (lane >> 4) << 3;
    const int rB = (lane & 7) + ((lane >> 4) << 3);
    const int cB = ((lane >> 3) & 1) << 3;

    float c[2][4][4];
#pragma unroll
    for (int i = 0; i < 2; i++)
#pragma unroll
        for (int j = 0; j < 4; j++)
#pragma unroll
            for (int r = 0; r < 4; r++) c[i][j][r] = 0.f;

    WV_LOAD(0, 0);
    for (int kb = 0; kb < 16; ++kb) {
        if (kb < 15) {
            WV_LOAD((kb + 1) & 1, kb + 1);
            asm volatile("cp.async.wait_group 1;" ::: "memory");
        } else {
            asm volatile("cp.async.wait_group 0;" ::: "memory");
        }
        __syncthreads();
        const uint32_t aS = aB + (uint32_t)(kb & 1) * WV_ASTG;
        const uint32_t bS = bB + (uint32_t)(kb & 1) * WV_BSTG;
#pragma unroll
        for (int ks = 0; ks < 4; ++ks) {
            uint32_t a[2][4];
#pragma unroll
            for (int i = 0; i < 2; i++)
                ldsm4(a[i], aS + (uint32_t)(((wm + i * 16 + rA) * 72 + cA + ks * 16) << 1));
            uint32_t bb[4][2];
#pragma unroll
            for (int j2 = 0; j2 < 2; j2++) {
                uint32_t r4[4];
                ldsm4(r4, bS + (uint32_t)(((wn + j2 * 16 + rB) * 72 + cB + ks * 16) << 1));
                bb[2 * j2 + 0][0] = r4[0]; bb[2 * j2 + 0][1] = r4[1];
                bb[2 * j2 + 1][0] = r4[2]; bb[2 * j2 + 1][1] = r4[3];
            }
#pragma unroll
            for (int i = 0; i < 2; i++)
#pragma unroll
                for (int j = 0; j < 4; j++)
                    mma16(c[i][j], a[i], bb[j]);
        }
        __syncthreads();
    }
#undef WV_LOAD

    const int gro = lane >> 2, gco = (lane & 3) << 1;
#pragma unroll
    for (int i = 0; i < 2; i++) {
        const int r0 = m0 + wm + i * 16 + gro;
        const float ps0 = psum[(size_t)r0 * 16 + h];
        const float ps1 = psum[(size_t)(r0 + 8) * 16 + h];
#pragma unroll
        for (int j = 0; j < 4; j++) {
            const int d = wn + j * 8 + gco;
            const float bv0 = sbv[d], bv1 = sbv[d + 1];
            float* p0 = merged + ((size_t)r0 << 10) + (h << 6) + d;
            float* p1 = merged + ((size_t)(r0 + 8) << 10) + (h << 6) + d;
            p0[0] = tf32r(p0[0] + c[i][j][0] + ps0 * bv0);
            p0[1] = tf32r(p0[1] + c[i][j][1] + ps0 * bv1);
            p1[0] = tf32r(p1[0] + c[i][j][2] + ps1 * bv0);
            p1[1] = tf32r(p1[1] + c[i][j][3] + ps1 * bv1);
        }
    }
}

// ---------------------------------------------------------------------------
// launch
// ---------------------------------------------------------------------------
extern "C" void kernel_launch(void* const* d_in, const int* in_sizes, int n_in,
                              void* d_out, int out_size)
{
    const float* x     = (const float*)d_in[0];
    const float* pastk = (const float*)d_in[1];
    const float* pastv = (const float*)d_in[2];
    const float* pastq = (const float*)d_in[3];
    const float* Wqkv  = (const float*)d_in[4];
    const float* bqkv  = (const float*)d_in[5];
    const float* Wout  = (const float*)d_in[6];
    const float* bout  = (const float*)d_in[7];

    float* out = (float*)d_out;                 // (B,S,D)
    float* oK  = out + (size_t)2097152;         // (B,H,S,hd)
    float* oV  = out + (size_t)2 * 2097152;
    float* oQ  = out + (size_t)3 * 2097152;

    static __half *s_memlnh = nullptr, *s_xh = nullptr, *s_wqkvh = nullptr;
    static __half *s_qh = nullptr, *s_kh = nullptr, *s_vh = nullptr;
    static __half *s_wkT = nullptr, *s_qp = nullptr, *s_ctx = nullptr;
    static float *s_ms = nullptr, *s_pmn = nullptr, *s_qb = nullptr;
    static float *s_psum = nullptr, *s_merged = nullptr, *s_wout = nullptr;
    if (!s_memlnh) {
        cudaGetSymbolAddress((void**)&s_memlnh, g_memlnh);
        cudaGetSymbolAddress((void**)&s_xh, g_xh);
        cudaGetSymbolAddress((void**)&s_wqkvh, g_wqkvh);
        cudaGetSymbolAddress((void**)&s_qh, g_qhh);
        cudaGetSymbolAddress((void**)&s_kh, g_khh);
        cudaGetSymbolAddress((void**)&s_vh, g_vhh);
        cudaGetSymbolAddress((void**)&s_wkT, g_wkT);
        cudaGetSymbolAddress((void**)&s_qp, g_qp);
        cudaGetSymbolAddress((void**)&s_ctx, g_ctx);
        cudaGetSymbolAddress((void**)&s_ms, g_ms);
        cudaGetSymbolAddress((void**)&s_pmn, g_pmn);
        cudaGetSymbolAddress((void**)&s_qb, g_qb);
        cudaGetSymbolAddress((void**)&s_psum, g_psum);
        cudaGetSymbolAddress((void**)&s_merged, g_merged);
        cudaGetSymbolAddress((void**)&s_wout, g_wout);
        cudaFuncSetAttribute(gemm_qkv, cudaFuncAttributeMaxDynamicSharedMemorySize,
                             GF_SMEM);
        cudaFuncSetAttribute(k_wv, cudaFuncAttributeMaxDynamicSharedMemorySize,
                             WV_SMEM);
    }

    // 0) operand conversion
    cvt_fp16_kernel<<<2048, 256>>>((const float4*)x,    (__half2*)s_xh);
    cvt_fp16_kernel<<<3072, 256>>>((const float4*)Wqkv, (__half2*)s_wqkvh);
    cvt_tf32_kernel<<<1024, 256>>>((const float4*)Wout, (float4*)s_wout);
    {
        dim3 g(32, 32); dim3 blk(32, 8);
        k_wkT<<<g, blk>>>(Wqkv + (size_t)1024 * 1024, s_wkT);
    }

    // 1) qkv projection
    {
        dim3 g(3072 / 128, 2048 / 256);
        gemm_qkv<<<g, 256, GF_SMEM>>>(s_xh, s_wqkvh, bqkv, oQ, oK, oV,
                                      s_qh, s_kh, s_vh);
    }
    // 2) mem gather + LayerNorm -> fp16
    mem_ln_kernel<<<24576, 256>>>(pastq, pastk, pastv);
    // 3) per-head q projection, bias dots, mem scores
    {
        dim3 g(8, 8, 32);
        k_qp<<<g, 256>>>(s_qh, s_wkT, s_qp);
    }
    k_qb<<<32, 256>>>(s_qh, bqkv, s_qb);
    k_ms<<<2048, 512>>>(s_qp, s_memlnh, s_qb, s_ms);
    // 4) flash attention + merge
    {
        dim3 g(BATCH * NHEAD, 16);
        attn_fa<<<g, 128>>>(s_qh, s_kh, s_vh, s_ms, s_pmn, s_merged);
    }
    // 5) memory context: combine memln, apply Wv, accumulate into merged
    k_ctx<<<2048, 256>>>(s_pmn, s_memlnh, s_ctx, s_psum);
    {
        dim3 g(16, 16);
        k_wv<<<g, 256, WV_SMEM>>>(s_ctx, s_wqkvh, s_psum, bqkv, s_merged);
    }
    // 6) output projection
    {
        dim3 g(1024 / 128, 2048 / 128);
        gemm_tf32<<<g, 256>>>(s_merged, s_wout, bout, out, 2048, 1024, 1024);
    }
}